// round 10
// baseline (speedup 1.0000x reference)
#include <cuda_runtime.h>
#include <math.h>

#define Bsz 32
#define Nf  4096
#define Kv  1024
#define Dm  1024
#define Hh  16
#define MAXF 4096

typedef unsigned long long u64;

// Single static scratch arena — no allocations anywhere.
__device__ float g_scratch[16777216];

// ---- f32x2 packed helpers ---------------------------------------------------
__device__ __forceinline__ void ffma2(u64& d, u64 a, u64 b)
{
    asm("fma.rn.f32x2 %0, %1, %2, %0;" : "+l"(d) : "l"(a), "l"(b));
}
__device__ __forceinline__ u64 dup2(float a)
{
    u64 r; asm("mov.b64 %0, {%1,%1};" : "=l"(r) : "f"(a)); return r;
}
__device__ __forceinline__ float sum2(u64 v)
{
    float lo, hi; asm("mov.b64 {%0,%1}, %2;" : "=f"(lo), "=f"(hi) : "l"(v));
    return lo + hi;
}
__device__ __forceinline__ float f4c(const float4& v, int c)
{
    return c == 0 ? v.x : c == 1 ? v.y : c == 2 ? v.z : v.w;
}

// ---------------- mean over frame tokens (split into 16 partials) -------------
__global__ void k_mean_part(const float* __restrict__ frame, float* __restrict__ mpart)
{
    int b = blockIdx.x, sp = blockIdx.y, tid = threadIdx.x;
    const float4* fp = (const float4*)(frame + ((size_t)b * Nf + sp * 256) * Dm) + tid;
    float4 acc = make_float4(0.f, 0.f, 0.f, 0.f);
    #pragma unroll 4
    for (int n = 0; n < 256; n++) {
        float4 v = fp[(size_t)n * 256];
        acc.x += v.x; acc.y += v.y; acc.z += v.z; acc.w += v.w;
    }
    ((float4*)(mpart + ((size_t)sp * Bsz + b) * Dm))[tid] = acc;
}

// ---------------- q init ------------------------------------------------------
__global__ void k_qinit(const float* __restrict__ mpart, const float* __restrict__ mi,
                        const float* __restrict__ qb, const float* __restrict__ role,
                        const float* __restrict__ tw, const int* __restrict__ fidx,
                        float* __restrict__ q)
{
    int b = blockIdx.x, tid = threadIdx.x;
    float4 m = make_float4(0.f, 0.f, 0.f, 0.f);
    for (int sp = 0; sp < 16; sp++) {
        float4 v = ((const float4*)(mpart + ((size_t)sp * Bsz + b) * Dm))[tid];
        m.x += v.x; m.y += v.y; m.z += v.z; m.w += v.w;
    }
    const float inv = 1.f / (float)Nf;
    int t = fidx[b]; t = t < 0 ? 0 : (t > MAXF - 1 ? MAXF - 1 : t);
    float4 te = ((const float4*)(tw + (size_t)t * Dm))[tid];
    float4 q0 = ((const float4*)qb)[tid];
    float4 q1 = ((const float4*)(qb + Dm))[tid];
    float4 r0 = ((const float4*)role)[tid];
    float4 r1 = ((const float4*)(role + Dm))[tid];
    float4 mv = ((const float4*)(mi + (size_t)b * Dm))[tid];
    float4 o0, o1;
    o0.x = m.x * inv + q0.x + r0.x + te.x;  o0.y = m.y * inv + q0.y + r0.y + te.y;
    o0.z = m.z * inv + q0.z + r0.z + te.z;  o0.w = m.w * inv + q0.w + r0.w + te.w;
    o1.x = mv.x + q1.x + r1.x + te.x;       o1.y = mv.y + q1.y + r1.y + te.y;
    o1.z = mv.z + q1.z + r1.z + te.z;       o1.w = mv.w + q1.w + r1.w + te.w;
    ((float4*)(q + (size_t)b * 2 * Dm))[tid] = o0;
    ((float4*)(q + (size_t)b * 2 * Dm + Dm))[tid] = o1;
}

// ---------------- LayerNorm (+ optional transposed output) -------------------
__global__ void k_ln(const float* __restrict__ in, const float* __restrict__ g,
                     const float* __restrict__ b, float* __restrict__ outp,
                     float* __restrict__ outT)
{
    __shared__ float2 red[256];
    int row = blockIdx.x, tid = threadIdx.x;
    float4 v = ((const float4*)(in + (size_t)row * Dm))[tid];
    float s = v.x + v.y + v.z + v.w;
    float sq = v.x * v.x + v.y * v.y + v.z * v.z + v.w * v.w;
    red[tid] = make_float2(s, sq); __syncthreads();
    for (int st = 128; st > 0; st >>= 1) {
        if (tid < st) { red[tid].x += red[tid + st].x; red[tid].y += red[tid + st].y; }
        __syncthreads();
    }
    float mean = red[0].x * (1.f / 1024.f);
    float var  = red[0].y * (1.f / 1024.f) - mean * mean;
    float rstd = rsqrtf(var + 1e-5f);
    float4 gv = ((const float4*)g)[tid];
    float4 bv = ((const float4*)b)[tid];
    float4 o;
    o.x = (v.x - mean) * rstd * gv.x + bv.x;
    o.y = (v.y - mean) * rstd * gv.y + bv.y;
    o.z = (v.z - mean) * rstd * gv.z + bv.z;
    o.w = (v.w - mean) * rstd * gv.w + bv.w;
    ((float4*)(outp + (size_t)row * Dm))[tid] = o;
    if (outT) {
        int d = tid * 4;
        outT[(size_t)(d + 0) * 64 + row] = o.x;
        outT[(size_t)(d + 1) * 64 + row] = o.y;
        outT[(size_t)(d + 2) * 64 + row] = o.z;
        outT[(size_t)(d + 3) * 64 + row] = o.w;
    }
}

// ---------------- sync-free batched GEMV (weight streaming) ------------------
// part[ks][m][n] = A[m, kchunk] . W[n, kchunk], A given TRANSPOSED as AT[k][wid].
// MT=64: lane -> m = 2*lane, 2*lane+1 (float2 AT reads).
// MT=32: lane -> m = lane, AT column = lane*cstep + c0.
// Block: 256 thr = 8 warps, 4 n-rows per warp -> 32 n per block.
template<int MT>
__global__ __launch_bounds__(256) void k_gemv(
    const float* __restrict__ AT, int wid, int cstep, int c0,
    const float* __restrict__ W, int K,
    float* __restrict__ part, int N, int kchunk, int Mtot)
{
    int tid = threadIdx.x;
    int lane = tid & 31, w = tid >> 5;
    int n = blockIdx.x * 32 + w * 4;
    int k0 = blockIdx.z * kchunk;
    const float* W0 = W + (size_t)(n + 0) * K;
    const float* W1 = W + (size_t)(n + 1) * K;
    const float* W2 = W + (size_t)(n + 2) * K;
    const float* W3 = W + (size_t)(n + 3) * K;

    if (MT == 64) {
        float acc00 = 0.f, acc01 = 0.f, acc10 = 0.f, acc11 = 0.f;
        float acc20 = 0.f, acc21 = 0.f, acc30 = 0.f, acc31 = 0.f;
        const float* ATp = AT + 2 * lane;
        #pragma unroll 2
        for (int kk = k0; kk < k0 + kchunk; kk += 4) {
            float4 w0 = *(const float4*)(W0 + kk);
            float4 w1 = *(const float4*)(W1 + kk);
            float4 w2 = *(const float4*)(W2 + kk);
            float4 w3 = *(const float4*)(W3 + kk);
            #pragma unroll
            for (int c = 0; c < 4; c++) {
                float2 a = *(const float2*)(ATp + (size_t)(kk + c) * wid);
                float va = f4c(w0, c), vb = f4c(w1, c), vc = f4c(w2, c), vd = f4c(w3, c);
                acc00 += a.x * va; acc01 += a.y * va;
                acc10 += a.x * vb; acc11 += a.y * vb;
                acc20 += a.x * vc; acc21 += a.y * vc;
                acc30 += a.x * vd; acc31 += a.y * vd;
            }
        }
        float* P = part + (size_t)blockIdx.z * Mtot * N;
        int m0 = 2 * lane;
        P[(size_t)m0 * N + n + 0] = acc00; P[(size_t)(m0 + 1) * N + n + 0] = acc01;
        P[(size_t)m0 * N + n + 1] = acc10; P[(size_t)(m0 + 1) * N + n + 1] = acc11;
        P[(size_t)m0 * N + n + 2] = acc20; P[(size_t)(m0 + 1) * N + n + 2] = acc21;
        P[(size_t)m0 * N + n + 3] = acc30; P[(size_t)(m0 + 1) * N + n + 3] = acc31;
    } else {
        float a0 = 0.f, a1 = 0.f, a2 = 0.f, a3 = 0.f;
        const float* ATp = AT + lane * cstep + c0;
        #pragma unroll 2
        for (int kk = k0; kk < k0 + kchunk; kk += 4) {
            float4 w0 = *(const float4*)(W0 + kk);
            float4 w1 = *(const float4*)(W1 + kk);
            float4 w2 = *(const float4*)(W2 + kk);
            float4 w3 = *(const float4*)(W3 + kk);
            #pragma unroll
            for (int c = 0; c < 4; c++) {
                float a = ATp[(size_t)(kk + c) * wid];
                a0 += a * f4c(w0, c);
                a1 += a * f4c(w1, c);
                a2 += a * f4c(w2, c);
                a3 += a * f4c(w3, c);
            }
        }
        float* P = part + (size_t)blockIdx.z * Mtot * N + (size_t)lane * N + n;
        P[0] = a0; P[1] = a1; P[2] = a2; P[3] = a3;
    }
}

__device__ __forceinline__ float gelu_exact(float x)
{
    return 0.5f * x * (1.f + erff(x * 0.70710678118654752f));
}

// reduce split-K partials + bias (+ residual) (+ gelu) (+ transposed copy)
__global__ void k_gemm_reduce(const float* __restrict__ part,
                              float* __restrict__ C, int ldc,
                              const float* __restrict__ bias,
                              const float* __restrict__ Res, int ldr,
                              int M, int N, int nsplit, int act,
                              float* __restrict__ CT, int tw)
{
    int n = blockIdx.x * 256 + threadIdx.x;
    int m = blockIdx.y;
    if (n >= N) return;
    float s = 0.f;
    for (int ks = 0; ks < nsplit; ks++) s += part[((size_t)ks * M + m) * N + n];
    s += bias[n];
    if (Res) s += Res[(size_t)m * ldr + n];
    if (act) s = gelu_exact(s);
    C[(size_t)m * ldc + n] = s;
    if (CT) CT[(size_t)n * tw + m] = s;
}

// ---------------- 2-token self-attention core --------------------------------
__global__ void k_selfattn(const float* __restrict__ t3, float* __restrict__ attn,
                           float* __restrict__ attnT)
{
    int b = blockIdx.x, h = blockIdx.y, d = threadIdx.x;
    const float* r0 = t3 + (size_t)(b * 2 + 0) * 3072;
    const float* r1 = t3 + (size_t)(b * 2 + 1) * 3072;
    int j = h * 64 + d;
    float q0 = r0[j], k0 = r0[1024 + j], v0 = r0[2048 + j];
    float q1 = r1[j], k1 = r1[1024 + j], v1 = r1[2048 + j];
    __shared__ float sh[4][64];
    sh[0][d] = q0 * k0; sh[1][d] = q0 * k1; sh[2][d] = q1 * k0; sh[3][d] = q1 * k1;
    __syncthreads();
    for (int st = 32; st > 0; st >>= 1) {
        if (d < st) {
            #pragma unroll
            for (int i = 0; i < 4; i++) sh[i][d] += sh[i][d + st];
        }
        __syncthreads();
    }
    float s00 = sh[0][0] * 0.125f, s01 = sh[1][0] * 0.125f;
    float s10 = sh[2][0] * 0.125f, s11 = sh[3][0] * 0.125f;
    float m0 = fmaxf(s00, s01), m1 = fmaxf(s10, s11);
    float e00 = expf(s00 - m0), e01 = expf(s01 - m0);
    float e10 = expf(s10 - m1), e11 = expf(s11 - m1);
    float a00 = e00 / (e00 + e01), a01 = e01 / (e00 + e01);
    float a10 = e10 / (e10 + e11), a11 = e11 / (e10 + e11);
    float o0 = a00 * v0 + a01 * v1;
    float o1 = a10 * v0 + a11 * v1;
    attn[(size_t)(b * 2 + 0) * Dm + j] = o0;
    attn[(size_t)(b * 2 + 1) * Dm + j] = o1;
    attnT[(size_t)j * 64 + b * 2 + 0] = o0;
    attnT[(size_t)j * 64 + b * 2 + 1] = o1;
}

// ---------------- fold: u[b,h,:] = qp[b, h*64: ] @ wk_h ----------------------
__global__ void k_ufold(const float* __restrict__ qp, const float* __restrict__ wk,
                        float* __restrict__ u)
{
    int h = blockIdx.x;
    int e = blockIdx.y * 128 + threadIdx.x;
    __shared__ float qs[32][64];
    for (int i = threadIdx.x; i < 2048; i += 128)
        qs[i >> 6][i & 63] = qp[(size_t)(i >> 6) * Dm + h * 64 + (i & 63)];
    __syncthreads();
    float acc[32];
    #pragma unroll
    for (int b2 = 0; b2 < 32; b2++) acc[b2] = 0.f;
    for (int d = 0; d < 64; d++) {
        float w = wk[(size_t)(h * 64 + d) * Dm + e];
        #pragma unroll
        for (int b2 = 0; b2 < 32; b2++) acc[b2] += qs[b2][d] * w;
    }
    #pragma unroll
    for (int b2 = 0; b2 < 32; b2++) u[((size_t)b2 * Hh + h) * Dm + e] = acc[b2];
}

// ---------------- scores: s[b,h,n] = 0.125 * X[b,n,:] . u[b,h,:] -------------
__global__ __launch_bounds__(256) void k_scores(
    const float* __restrict__ X, const float* __restrict__ u,
    float* __restrict__ s, int Nt)
{
    extern __shared__ float ush[];   // 16*1024 floats = 64 KB
    int b = blockIdx.x, tid = threadIdx.x;
    const float4* usrc = (const float4*)(u + (size_t)b * Hh * Dm);
    #pragma unroll
    for (int i = 0; i < 16; i++) ((float4*)ush)[tid + i * 256] = usrc[tid + i * 256];
    __syncthreads();
    int w = tid >> 5, lane = tid & 31;
    for (int tl = 0; tl < 2; tl++) {
        int n0 = blockIdx.y * 64 + tl * 32 + w * 4;
        const ulonglong2* xp = (const ulonglong2*)(X + ((size_t)b * Nt + n0) * Dm);
        u64 acc[16][4];
        #pragma unroll
        for (int h = 0; h < 16; h++)
            #pragma unroll
            for (int t = 0; t < 4; t++) acc[h][t] = 0ULL;
        for (int i = 0; i < 8; i++) {
            ulonglong2 x0 = xp[0 * 256 + i * 32 + lane];
            ulonglong2 x1 = xp[1 * 256 + i * 32 + lane];
            ulonglong2 x2 = xp[2 * 256 + i * 32 + lane];
            ulonglong2 x3 = xp[3 * 256 + i * 32 + lane];
            #pragma unroll
            for (int h = 0; h < 16; h++) {
                ulonglong2 uv = *(const ulonglong2*)&ush[h * Dm + i * 128 + (lane << 2)];
                ffma2(acc[h][0], x0.x, uv.x); ffma2(acc[h][0], x0.y, uv.y);
                ffma2(acc[h][1], x1.x, uv.x); ffma2(acc[h][1], x1.y, uv.y);
                ffma2(acc[h][2], x2.x, uv.x); ffma2(acc[h][2], x2.y, uv.y);
                ffma2(acc[h][3], x3.x, uv.x); ffma2(acc[h][3], x3.y, uv.y);
            }
        }
        #pragma unroll
        for (int h = 0; h < 16; h++) {
            #pragma unroll
            for (int t = 0; t < 4; t++) {
                float v = sum2(acc[h][t]);
                #pragma unroll
                for (int off = 16; off; off >>= 1) v += __shfl_xor_sync(0xffffffffu, v, off);
                if (lane == 0) s[((size_t)b * Hh + h) * Nt + n0 + t] = v * 0.125f;
            }
        }
    }
}

// ---------------- row softmax over Nt ----------------------------------------
template <int CNT>
__global__ void k_softmax(float* __restrict__ s, int Nt)
{
    __shared__ float red[256];
    size_t base = (size_t)blockIdx.x * Nt;
    int tid = threadIdx.x;
    float v[CNT];
    float mx = -1e30f;
    #pragma unroll
    for (int i = 0; i < CNT; i++) { v[i] = s[base + i * 256 + tid]; mx = fmaxf(mx, v[i]); }
    red[tid] = mx; __syncthreads();
    for (int st = 128; st > 0; st >>= 1) {
        if (tid < st) red[tid] = fmaxf(red[tid], red[tid + st]);
        __syncthreads();
    }
    mx = red[0]; __syncthreads();
    float sum = 0.f;
    #pragma unroll
    for (int i = 0; i < CNT; i++) { v[i] = expf(v[i] - mx); sum += v[i]; }
    red[tid] = sum; __syncthreads();
    for (int st = 128; st > 0; st >>= 1) {
        if (tid < st) red[tid] += red[tid + st];
        __syncthreads();
    }
    float inv = 1.f / red[0];
    #pragma unroll
    for (int i = 0; i < CNT; i++) s[base + i * 256 + tid] = v[i] * inv;
}

// ---------------- wbar partials ----------------------------------------------
__global__ __launch_bounds__(256) void k_wbar_part(
    const float* __restrict__ X, const float* __restrict__ a,
    float* __restrict__ part, int Nt)
{
    __shared__ u64 ash2[256][17];
    int b = blockIdx.x, sp = blockIdx.y;
    int n0 = sp * 256;
    int tid = threadIdx.x;
    for (int idx = tid; idx < 4096; idx += 256) {
        int nn = idx & 255, h = idx >> 8;
        float av = a[((size_t)b * Hh + h) * Nt + n0 + nn];
        ash2[nn][h] = dup2(av);
    }
    __syncthreads();
    u64 acc[16][2];
    #pragma unroll
    for (int h = 0; h < 16; h++) { acc[h][0] = 0ULL; acc[h][1] = 0ULL; }
    const ulonglong2* xp = (const ulonglong2*)(X + ((size_t)b * Nt + n0) * Dm) + tid;
    for (int nn = 0; nn < 256; nn++) {
        ulonglong2 f = xp[(size_t)nn * 256];
        #pragma unroll
        for (int h = 0; h < 16; h++) {
            u64 aa = ash2[nn][h];
            ffma2(acc[h][0], aa, f.x);
            ffma2(acc[h][1], aa, f.y);
        }
    }
    ulonglong2* P = (ulonglong2*)(part + (((size_t)sp * Bsz + b) * Hh) * Dm);
    #pragma unroll
    for (int h = 0; h < 16; h++) {
        ulonglong2 v; v.x = acc[h][0]; v.y = acc[h][1];
        P[h * 256 + tid] = v;
    }
}

// ---------------- v-projection (fused split reduce, + transposed out) --------
__global__ void k_vproj(const float* __restrict__ part, int NS,
                        const float* __restrict__ wv,
                        const float* __restrict__ bv, float* __restrict__ o,
                        float* __restrict__ oT)
{
    __shared__ float wsh[1024];
    int b = blockIdx.x, h = blockIdx.y, tid = threadIdx.x;
    float4 acc4 = make_float4(0.f, 0.f, 0.f, 0.f);
    for (int sp = 0; sp < NS; sp++) {
        float4 v = ((const float4*)(part + (((size_t)sp * Bsz + b) * Hh + h) * Dm))[tid];
        acc4.x += v.x; acc4.y += v.y; acc4.z += v.z; acc4.w += v.w;
    }
    ((float4*)wsh)[tid] = acc4;
    __syncthreads();
    int w = tid >> 5, lane = tid & 31;
    for (int dd = w; dd < 64; dd += 8) {
        int j = h * 64 + dd;
        const float4* wvp = (const float4*)(wv + (size_t)j * Dm);
        float acc = 0.f;
        #pragma unroll
        for (int i = 0; i < 8; i++) {
            float4 a = wvp[i * 32 + lane];
            float4 c = *(const float4*)&wsh[i * 128 + (lane << 2)];
            acc += a.x * c.x + a.y * c.y + a.z * c.z + a.w * c.w;
        }
        #pragma unroll
        for (int off = 16; off; off >>= 1) acc += __shfl_xor_sync(0xffffffffu, acc, off);
        if (lane == 0) {
            float r = acc + bv[j];
            o[(size_t)b * Dm + j] = r;
            oT[(size_t)j * 32 + b] = r;
        }
    }
}

extern "C" void kernel_launch(void* const* d_in, const int* in_sizes, int n_in,
                              void* d_out, int out_size)
{
    const float* frame = (const float*)d_in[0];
    const float* kvs   = (const float*)d_in[1];
    const float* maxi  = (const float*)d_in[2];
    const float* qbase = (const float*)d_in[3];
    const float* role  = (const float*)d_in[4];
    const float* timew = (const float*)d_in[5];
    const float* ln1g  = (const float*)d_in[6];
    const float* ln1b  = (const float*)d_in[7];
    const float* sa_in_w = (const float*)d_in[8];
    const float* sa_in_b = (const float*)d_in[9];
    const float* sa_out_w = (const float*)d_in[10];
    const float* sa_out_b = (const float*)d_in[11];
    const float* ln2g  = (const float*)d_in[12];
    const float* ln2b  = (const float*)d_in[13];
    const float* cg_in_w = (const float*)d_in[14];
    const float* cg_in_b = (const float*)d_in[15];
    const float* cg_out_w = (const float*)d_in[16];
    const float* cg_out_b = (const float*)d_in[17];
    const float* cs_in_w = (const float*)d_in[18];
    const float* cs_in_b = (const float*)d_in[19];
    const float* cs_out_w = (const float*)d_in[20];
    const float* cs_out_b = (const float*)d_in[21];
    const float* ln3g  = (const float*)d_in[22];
    const float* ln3b  = (const float*)d_in[23];
    const float* fw1   = (const float*)d_in[24];
    const float* fb1   = (const float*)d_in[25];
    const float* fw2   = (const float*)d_in[26];
    const float* fb2   = (const float*)d_in[27];
    const float* outg  = (const float*)d_in[28];
    const float* outb  = (const float*)d_in[29];
    const int*   fidx  = (const int*)d_in[30];
    float* outp = (float*)d_out;

    void* sp_;
    cudaGetSymbolAddress(&sp_, g_scratch);
    float* S = (float*)sp_;
    float* mpart = S;                   // 524288
    float* q     = mpart + 524288;      // 65536
    float* x     = q + 65536;           // 65536
    float* xT    = x + 65536;           // 65536
    float* t3    = xT + 65536;          // 196608
    float* attn  = t3 + 196608;         // 65536
    float* attnT = attn + 65536;        // 65536
    float* qpg   = attnT + 65536;       // 32768
    float* qps   = qpg + 32768;         // 32768
    float* ug    = qps + 32768;         // 524288
    float* us    = ug + 524288;         // 524288
    float* sg    = us + 524288;         // 2097152
    float* ss    = sg + 2097152;        // 524288
    float* wpart = ss + 524288;         // 8388608
    float* og    = wpart + 8388608;     // 32768
    float* ogT   = og + 32768;          // 32768
    float* os    = ogT + 32768;         // 32768
    float* osT   = os + 32768;          // 32768
    float* gpart = osT + 32768;         // 2097152
    float* hh    = gpart + 2097152;     // 262144
    float* hhT   = hh + 262144;         // 262144

    cudaFuncSetAttribute(k_scores, cudaFuncAttributeMaxDynamicSharedMemorySize, 65536);

    // init: mean + q assembly
    k_mean_part<<<dim3(32, 16), 256>>>(frame, mpart);
    k_qinit<<<32, 256>>>(mpart, maxi, qbase, role, timew, fidx, q);

    for (int l = 0; l < 2; l++) {
        const float* l1g = ln1g + l * Dm;   const float* l1b = ln1b + l * Dm;
        const float* siw = sa_in_w + (size_t)l * 3072 * Dm;
        const float* sib = sa_in_b + l * 3072;
        const float* sow = sa_out_w + (size_t)l * Dm * Dm;
        const float* sob = sa_out_b + l * Dm;
        const float* l2g = ln2g + l * Dm;   const float* l2b = ln2b + l * Dm;
        const float* giw = cg_in_w + (size_t)l * 3072 * Dm;
        const float* gib = cg_in_b + l * 3072;
        const float* gow = cg_out_w + (size_t)l * Dm * Dm;
        const float* gob = cg_out_b + l * Dm;
        const float* ciw = cs_in_w + (size_t)l * 3072 * Dm;
        const float* cib = cs_in_b + l * 3072;
        const float* cow = cs_out_w + (size_t)l * Dm * Dm;
        const float* cob = cs_out_b + l * Dm;
        const float* l3g = ln3g + l * Dm;   const float* l3b = ln3b + l * Dm;
        const float* w1 = fw1 + (size_t)l * 4096 * Dm;
        const float* b1 = fb1 + l * 4096;
        const float* w2 = fw2 + (size_t)l * Dm * 4096;
        const float* b2 = fb2 + l * Dm;

        // ---- self-attention (2 tokens) ----
        k_ln<<<64, 256>>>(q, l1g, l1b, x, xT);
        k_gemv<64><<<dim3(96, 1, 2), 256>>>(xT, 64, 1, 0, siw, 1024, gpart, 3072, 512, 64);
        k_gemm_reduce<<<dim3(12, 64), 256>>>(gpart, t3, 3072, sib, nullptr, 0,
                                             64, 3072, 2, 0, nullptr, 0);
        k_selfattn<<<dim3(32, 16), 64>>>(t3, attn, attnT);
        k_gemv<64><<<dim3(32, 1, 8), 256>>>(attnT, 64, 1, 0, sow, 1024, gpart, 1024, 128, 64);
        k_gemm_reduce<<<dim3(4, 64), 256>>>(gpart, q, 1024, sob, q, 1024,
                                            64, 1024, 8, 0, nullptr, 0);

        // ---- cross-attention (folded K/V) ----
        k_ln<<<64, 256>>>(q, l2g, l2b, x, xT);
        k_gemv<32><<<dim3(32, 1, 8), 256>>>(xT, 64, 2, 0, giw, 1024, gpart, 1024, 128, 32);
        k_gemm_reduce<<<dim3(4, 32), 256>>>(gpart, qpg, 1024, gib, nullptr, 0,
                                            32, 1024, 8, 0, nullptr, 0);
        k_gemv<32><<<dim3(32, 1, 8), 256>>>(xT, 64, 2, 1, ciw, 1024, gpart, 1024, 128, 32);
        k_gemm_reduce<<<dim3(4, 32), 256>>>(gpart, qps, 1024, cib, nullptr, 0,
                                            32, 1024, 8, 0, nullptr, 0);
        k_ufold<<<dim3(16, 8), 128>>>(qpg, giw + 1024 * 1024, ug);
        k_ufold<<<dim3(16, 8), 128>>>(qps, ciw + 1024 * 1024, us);
        k_scores<<<dim3(32, 64), 256, 65536>>>(frame, ug, sg, Nf);
        k_scores<<<dim3(32, 16), 256, 65536>>>(kvs, us, ss, Kv);
        k_softmax<16><<<512, 256>>>(sg, Nf);
        k_softmax<4><<<512, 256>>>(ss, Kv);
        k_wbar_part<<<dim3(32, 16), 256>>>(frame, sg, wpart, Nf);
        k_vproj<<<dim3(32, 16), 256>>>(wpart, 16, giw + 2 * 1024 * 1024, gib + 2048, og, ogT);
        k_wbar_part<<<dim3(32, 4), 256>>>(kvs, ss, wpart, Kv);
        k_vproj<<<dim3(32, 16), 256>>>(wpart, 4, ciw + 2 * 1024 * 1024, cib + 2048, os, osT);
        k_gemv<32><<<dim3(32, 1, 8), 256>>>(ogT, 32, 1, 0, gow, 1024, gpart, 1024, 128, 32);
        k_gemm_reduce<<<dim3(4, 32), 256>>>(gpart, q, 2048, gob, q, 2048,
                                            32, 1024, 8, 0, nullptr, 0);
        k_gemv<32><<<dim3(32, 1, 8), 256>>>(osT, 32, 1, 0, cow, 1024, gpart, 1024, 128, 32);
        k_gemm_reduce<<<dim3(4, 32), 256>>>(gpart, q + 1024, 2048, cob, q + 1024, 2048,
                                            32, 1024, 8, 0, nullptr, 0);

        // ---- FFN ----
        k_ln<<<64, 256>>>(q, l3g, l3b, x, xT);
        k_gemv<64><<<dim3(128, 1, 2), 256>>>(xT, 64, 1, 0, w1, 1024, gpart, 4096, 512, 64);
        k_gemm_reduce<<<dim3(16, 64), 256>>>(gpart, hh, 4096, b1, nullptr, 0,
                                             64, 4096, 2, 1, hhT, 64);
        k_gemv<64><<<dim3(32, 1, 8), 256>>>(hhT, 64, 1, 0, w2, 4096, gpart, 1024, 512, 64);
        k_gemm_reduce<<<dim3(4, 64), 256>>>(gpart, q, 1024, b2, q, 1024,
                                            64, 1024, 8, 0, nullptr, 0);
    }

    // final LN -> d_out (B,2,D) contiguous
    k_ln<<<64, 256>>>(q, outg, outb, outp, nullptr);
}

// round 11
// speedup vs baseline: 1.6527x; 1.6527x over previous
#include <cuda_runtime.h>
#include <math.h>

#define Bsz 32
#define Nf  4096
#define Kv  1024
#define Dm  1024
#define Hh  16
#define MAXF 4096

typedef unsigned long long u64;

// Single static scratch arena — no allocations anywhere.
__device__ float g_scratch[16777216];

// ---- f32x2 packed helpers ---------------------------------------------------
__device__ __forceinline__ void ffma2(u64& d, u64 a, u64 b)
{
    asm("fma.rn.f32x2 %0, %1, %2, %0;" : "+l"(d) : "l"(a), "l"(b));
}
__device__ __forceinline__ u64 dup2(float a)
{
    u64 r; asm("mov.b64 %0, {%1,%1};" : "=l"(r) : "f"(a)); return r;
}
// pack two fp32 -> bf16x2 (lo = first)
__device__ __forceinline__ unsigned bfpack(float lo, float hi)
{
    unsigned r;
    asm("cvt.rn.bf16x2.f32 %0, %1, %2;" : "=r"(r) : "f"(hi), "f"(lo));
    return r;
}
#define MMA_BF16(c, a0, a1, a2, a3, b0, b1) \
    asm("mma.sync.aligned.m16n8k16.row.col.f32.bf16.bf16.f32 " \
        "{%0,%1,%2,%3}, {%4,%5,%6,%7}, {%8,%9}, {%0,%1,%2,%3};" \
        : "+f"((c)[0]), "+f"((c)[1]), "+f"((c)[2]), "+f"((c)[3]) \
        : "r"(a0), "r"(a1), "r"(a2), "r"(a3), "r"(b0), "r"(b1))

// ---------------- mean over frame tokens (split into 16 partials) -------------
__global__ void k_mean_part(const float* __restrict__ frame, float* __restrict__ mpart)
{
    int b = blockIdx.x, sp = blockIdx.y, tid = threadIdx.x;
    const float4* fp = (const float4*)(frame + ((size_t)b * Nf + sp * 256) * Dm) + tid;
    float4 acc = make_float4(0.f, 0.f, 0.f, 0.f);
    #pragma unroll 4
    for (int n = 0; n < 256; n++) {
        float4 v = fp[(size_t)n * 256];
        acc.x += v.x; acc.y += v.y; acc.z += v.z; acc.w += v.w;
    }
    ((float4*)(mpart + ((size_t)sp * Bsz + b) * Dm))[tid] = acc;
}

// ---------------- q init ------------------------------------------------------
__global__ void k_qinit(const float* __restrict__ mpart, const float* __restrict__ mi,
                        const float* __restrict__ qb, const float* __restrict__ role,
                        const float* __restrict__ tw, const int* __restrict__ fidx,
                        float* __restrict__ q)
{
    int b = blockIdx.x, tid = threadIdx.x;
    float4 m = make_float4(0.f, 0.f, 0.f, 0.f);
    for (int sp = 0; sp < 16; sp++) {
        float4 v = ((const float4*)(mpart + ((size_t)sp * Bsz + b) * Dm))[tid];
        m.x += v.x; m.y += v.y; m.z += v.z; m.w += v.w;
    }
    const float inv = 1.f / (float)Nf;
    int t = fidx[b]; t = t < 0 ? 0 : (t > MAXF - 1 ? MAXF - 1 : t);
    float4 te = ((const float4*)(tw + (size_t)t * Dm))[tid];
    float4 q0 = ((const float4*)qb)[tid];
    float4 q1 = ((const float4*)(qb + Dm))[tid];
    float4 r0 = ((const float4*)role)[tid];
    float4 r1 = ((const float4*)(role + Dm))[tid];
    float4 mv = ((const float4*)(mi + (size_t)b * Dm))[tid];
    float4 o0, o1;
    o0.x = m.x * inv + q0.x + r0.x + te.x;  o0.y = m.y * inv + q0.y + r0.y + te.y;
    o0.z = m.z * inv + q0.z + r0.z + te.z;  o0.w = m.w * inv + q0.w + r0.w + te.w;
    o1.x = mv.x + q1.x + r1.x + te.x;       o1.y = mv.y + q1.y + r1.y + te.y;
    o1.z = mv.z + q1.z + r1.z + te.z;       o1.w = mv.w + q1.w + r1.w + te.w;
    ((float4*)(q + (size_t)b * 2 * Dm))[tid] = o0;
    ((float4*)(q + (size_t)b * 2 * Dm + Dm))[tid] = o1;
}

// ---------------- LayerNorm ---------------------------------------------------
__global__ void k_ln(const float* __restrict__ in, const float* __restrict__ g,
                     const float* __restrict__ b, float* __restrict__ outp)
{
    __shared__ float2 red[256];
    int row = blockIdx.x, tid = threadIdx.x;
    float4 v = ((const float4*)(in + (size_t)row * Dm))[tid];
    float s = v.x + v.y + v.z + v.w;
    float sq = v.x * v.x + v.y * v.y + v.z * v.z + v.w * v.w;
    red[tid] = make_float2(s, sq); __syncthreads();
    for (int st = 128; st > 0; st >>= 1) {
        if (tid < st) { red[tid].x += red[tid + st].x; red[tid].y += red[tid + st].y; }
        __syncthreads();
    }
    float mean = red[0].x * (1.f / 1024.f);
    float var  = red[0].y * (1.f / 1024.f) - mean * mean;
    float rstd = rsqrtf(var + 1e-5f);
    float4 gv = ((const float4*)g)[tid];
    float4 bv = ((const float4*)b)[tid];
    float4 o;
    o.x = (v.x - mean) * rstd * gv.x + bv.x;
    o.y = (v.y - mean) * rstd * gv.y + bv.y;
    o.z = (v.z - mean) * rstd * gv.z + bv.z;
    o.w = (v.w - mean) * rstd * gv.w + bv.w;
    ((float4*)(outp + (size_t)row * Dm))[tid] = o;
}

// ---------------- small GEMM (measured-best R2 schedule) ---------------------
__global__ __launch_bounds__(256) void k_gemm_part(
    const float* __restrict__ A, int lda, int M,
    const float* __restrict__ W,
    float* __restrict__ part, int N, int K, int kchunk)
{
    __shared__ float As[16][64];
    __shared__ float Ws[16][64];
    int tid = threadIdx.x;
    int n0 = blockIdx.x * 64;
    int ks = blockIdx.y;
    int ty = tid >> 4, tx = tid & 15;
    int lm = tid >> 2;
    int lk = (tid & 3) << 2;
    u64 acc[4][2];
    #pragma unroll
    for (int i = 0; i < 4; i++) { acc[i][0] = 0ULL; acc[i][1] = 0ULL; }

    const float* Ap = A + (size_t)lm * lda;
    const float* Wp = W + (size_t)(n0 + lm) * K;
    int kend = ks * kchunk + kchunk;
    for (int kk = ks * kchunk; kk < kend; kk += 16) {
        float4 av = make_float4(0.f, 0.f, 0.f, 0.f);
        if (lm < M) av = *(const float4*)(Ap + kk + lk);
        float4 wv = *(const float4*)(Wp + kk + lk);
        __syncthreads();
        As[lk + 0][lm] = av.x; As[lk + 1][lm] = av.y; As[lk + 2][lm] = av.z; As[lk + 3][lm] = av.w;
        Ws[lk + 0][lm] = wv.x; Ws[lk + 1][lm] = wv.y; Ws[lk + 2][lm] = wv.z; Ws[lk + 3][lm] = wv.w;
        __syncthreads();
        #pragma unroll
        for (int k2 = 0; k2 < 16; k2++) {
            float4 a = *(const float4*)&As[k2][ty << 2];
            ulonglong2 w = *(const ulonglong2*)&Ws[k2][tx << 2];
            u64 d0 = dup2(a.x), d1 = dup2(a.y), d2 = dup2(a.z), d3 = dup2(a.w);
            ffma2(acc[0][0], d0, w.x); ffma2(acc[0][1], d0, w.y);
            ffma2(acc[1][0], d1, w.x); ffma2(acc[1][1], d1, w.y);
            ffma2(acc[2][0], d2, w.x); ffma2(acc[2][1], d2, w.y);
            ffma2(acc[3][0], d3, w.x); ffma2(acc[3][1], d3, w.y);
        }
    }
    float* P = part + (size_t)ks * M * N;
    #pragma unroll
    for (int i = 0; i < 4; i++) {
        int m = (ty << 2) + i;
        if (m < M) {
            ulonglong2* row = (ulonglong2*)(P + (size_t)m * N + n0 + (tx << 2));
            ulonglong2 v; v.x = acc[i][0]; v.y = acc[i][1];
            *row = v;
        }
    }
}

__device__ __forceinline__ float gelu_exact(float x)
{
    return 0.5f * x * (1.f + erff(x * 0.70710678118654752f));
}

__global__ void k_gemm_reduce(const float* __restrict__ part,
                              float* __restrict__ C, int ldc,
                              const float* __restrict__ bias,
                              const float* __restrict__ Res, int ldr,
                              int M, int N, int nsplit, int act)
{
    int n = blockIdx.x * 256 + threadIdx.x;
    int m = blockIdx.y;
    if (n >= N) return;
    float s = 0.f;
    for (int ks = 0; ks < nsplit; ks++) s += part[((size_t)ks * M + m) * N + n];
    s += bias[n];
    if (Res) s += Res[(size_t)m * ldr + n];
    if (act) s = gelu_exact(s);
    C[(size_t)m * ldc + n] = s;
}

// ---------------- 2-token self-attention core --------------------------------
__global__ void k_selfattn(const float* __restrict__ t3, float* __restrict__ attn)
{
    int b = blockIdx.x, h = blockIdx.y, d = threadIdx.x;
    const float* r0 = t3 + (size_t)(b * 2 + 0) * 3072;
    const float* r1 = t3 + (size_t)(b * 2 + 1) * 3072;
    int j = h * 64 + d;
    float q0 = r0[j], k0 = r0[1024 + j], v0 = r0[2048 + j];
    float q1 = r1[j], k1 = r1[1024 + j], v1 = r1[2048 + j];
    __shared__ float sh[4][64];
    sh[0][d] = q0 * k0; sh[1][d] = q0 * k1; sh[2][d] = q1 * k0; sh[3][d] = q1 * k1;
    __syncthreads();
    for (int st = 32; st > 0; st >>= 1) {
        if (d < st) {
            #pragma unroll
            for (int i = 0; i < 4; i++) sh[i][d] += sh[i][d + st];
        }
        __syncthreads();
    }
    float s00 = sh[0][0] * 0.125f, s01 = sh[1][0] * 0.125f;
    float s10 = sh[2][0] * 0.125f, s11 = sh[3][0] * 0.125f;
    float m0 = fmaxf(s00, s01), m1 = fmaxf(s10, s11);
    float e00 = expf(s00 - m0), e01 = expf(s01 - m0);
    float e10 = expf(s10 - m1), e11 = expf(s11 - m1);
    float a00 = e00 / (e00 + e01), a01 = e01 / (e00 + e01);
    float a10 = e10 / (e10 + e11), a11 = e11 / (e10 + e11);
    attn[(size_t)(b * 2 + 0) * Dm + j] = a00 * v0 + a01 * v1;
    attn[(size_t)(b * 2 + 1) * Dm + j] = a10 * v0 + a11 * v1;
}

// ---------------- fold: u[b,h,:] = qp[b, h*64: ] @ wk_h ----------------------
__global__ void k_ufold(const float* __restrict__ qp, const float* __restrict__ wk,
                        float* __restrict__ u)
{
    int h = blockIdx.x;
    int e = blockIdx.y * 128 + threadIdx.x;
    __shared__ float qs[32][64];
    for (int i = threadIdx.x; i < 2048; i += 128)
        qs[i >> 6][i & 63] = qp[(size_t)(i >> 6) * Dm + h * 64 + (i & 63)];
    __syncthreads();
    float acc[32];
    #pragma unroll
    for (int b2 = 0; b2 < 32; b2++) acc[b2] = 0.f;
    for (int d = 0; d < 64; d++) {
        float w = wk[(size_t)(h * 64 + d) * Dm + e];
        #pragma unroll
        for (int b2 = 0; b2 < 32; b2++) acc[b2] += qs[b2][d] * w;
    }
    #pragma unroll
    for (int b2 = 0; b2 < 32; b2++) u[((size_t)b2 * Hh + h) * Dm + e] = acc[b2];
}

// ---------------- scores via mma.sync bf16 -----------------------------------
// s[b,h,n] = 0.125 * X[b,n,:] . u[b,h,:]
// warp = 16 tokens x 16 heads; block = 8 warps = 128 tokens.
__global__ __launch_bounds__(256) void k_scores_mma(
    const float* __restrict__ X, const float* __restrict__ u,
    float* __restrict__ s, int Nt)
{
    __shared__ unsigned short ush[16][1032];   // bf16 u, row-padded (2064B rows)
    int b = blockIdx.x, tid = threadIdx.x;
    const float2* up = (const float2*)(u + (size_t)b * Hh * Dm);
    for (int i = tid; i < 8192; i += 256) {
        int h = i >> 9, d2 = i & 511;
        float2 v = up[(size_t)h * 512 + d2];
        *(unsigned*)&ush[h][d2 * 2] = bfpack(v.x, v.y);
    }
    __syncthreads();
    int w = tid >> 5, lane = tid & 31;
    int g = lane >> 2, t = lane & 3;
    int tok0 = (blockIdx.y * 8 + w) * 16;
    const float* r0 = X + ((size_t)b * Nt + tok0 + g) * Dm + 2 * t;
    const float* r1 = r0 + 8 * Dm;
    float c0[4] = {0.f, 0.f, 0.f, 0.f};
    float c1[4] = {0.f, 0.f, 0.f, 0.f};
    #pragma unroll 4
    for (int k0 = 0; k0 < 1024; k0 += 16) {
        float2 v0 = *(const float2*)(r0 + k0);
        float2 v1 = *(const float2*)(r1 + k0);
        float2 v2 = *(const float2*)(r0 + k0 + 8);
        float2 v3 = *(const float2*)(r1 + k0 + 8);
        unsigned a0 = bfpack(v0.x, v0.y);
        unsigned a1 = bfpack(v1.x, v1.y);
        unsigned a2 = bfpack(v2.x, v2.y);
        unsigned a3 = bfpack(v3.x, v3.y);
        unsigned b0 = *(const unsigned*)&ush[g][k0 + 2 * t];
        unsigned b1 = *(const unsigned*)&ush[g][k0 + 2 * t + 8];
        MMA_BF16(c0, a0, a1, a2, a3, b0, b1);
        unsigned b2 = *(const unsigned*)&ush[8 + g][k0 + 2 * t];
        unsigned b3 = *(const unsigned*)&ush[8 + g][k0 + 2 * t + 8];
        MMA_BF16(c1, a0, a1, a2, a3, b2, b3);
    }
    size_t sb = (size_t)b * Hh;
    const float sc = 0.125f;
    s[(sb + 2 * t    ) * Nt + tok0 + g    ] = c0[0] * sc;
    s[(sb + 2 * t + 1) * Nt + tok0 + g    ] = c0[1] * sc;
    s[(sb + 2 * t    ) * Nt + tok0 + g + 8] = c0[2] * sc;
    s[(sb + 2 * t + 1) * Nt + tok0 + g + 8] = c0[3] * sc;
    s[(sb + 8 + 2 * t    ) * Nt + tok0 + g    ] = c1[0] * sc;
    s[(sb + 8 + 2 * t + 1) * Nt + tok0 + g    ] = c1[1] * sc;
    s[(sb + 8 + 2 * t    ) * Nt + tok0 + g + 8] = c1[2] * sc;
    s[(sb + 8 + 2 * t + 1) * Nt + tok0 + g + 8] = c1[3] * sc;
}

// ---------------- row softmax over Nt ----------------------------------------
template <int CNT>
__global__ void k_softmax(float* __restrict__ s, int Nt)
{
    __shared__ float red[256];
    size_t base = (size_t)blockIdx.x * Nt;
    int tid = threadIdx.x;
    float v[CNT];
    float mx = -1e30f;
    #pragma unroll
    for (int i = 0; i < CNT; i++) { v[i] = s[base + i * 256 + tid]; mx = fmaxf(mx, v[i]); }
    red[tid] = mx; __syncthreads();
    for (int st = 128; st > 0; st >>= 1) {
        if (tid < st) red[tid] = fmaxf(red[tid], red[tid + st]);
        __syncthreads();
    }
    mx = red[0]; __syncthreads();
    float sum = 0.f;
    #pragma unroll
    for (int i = 0; i < CNT; i++) { v[i] = expf(v[i] - mx); sum += v[i]; }
    red[tid] = sum; __syncthreads();
    for (int st = 128; st > 0; st >>= 1) {
        if (tid < st) red[tid] += red[tid + st];
        __syncthreads();
    }
    float inv = 1.f / red[0];
    #pragma unroll
    for (int i = 0; i < CNT; i++) s[base + i * 256 + tid] = v[i] * inv;
}

// ---------------- wbar via mma.sync bf16 -------------------------------------
// part[sp][b][h][e] = sum_{n in 256-chunk} a[b,h,n] * X[b,n,e]
// block = (b, chunk); 8 warps, warp owns 128 e; 16 stages of 16 tokens.
__global__ __launch_bounds__(256) void k_wbar_mma(
    const float* __restrict__ X, const float* __restrict__ a,
    float* __restrict__ part, int Nt)
{
    __shared__ unsigned short ash[16][264];    // att weights bf16 [h][tok], 528B rows
    __shared__ unsigned short fsh[1024][18];   // frame^T bf16 [e][tok16], 36B rows
    int b = blockIdx.x, sp = blockIdx.y, tid = threadIdx.x;
    int n0 = sp * 256;
    // stage attention weights: 16 h x 256 tok
    for (int i = tid; i < 2048; i += 256) {
        int h = i >> 7, t2 = i & 127;
        float2 v = *(const float2*)(a + ((size_t)b * Hh + h) * Nt + n0 + t2 * 2);
        *(unsigned*)&ash[h][t2 * 2] = bfpack(v.x, v.y);
    }
    int w = tid >> 5, lane = tid & 31;
    int g = lane >> 2, t = lane & 3;
    float c[16][4];
    #pragma unroll
    for (int nb = 0; nb < 16; nb++) {
        c[nb][0] = 0.f; c[nb][1] = 0.f; c[nb][2] = 0.f; c[nb][3] = 0.f;
    }

    for (int st = 0; st < 16; st++) {
        __syncthreads();
        // stage X[16 tok][1024 e] -> fsh[e][tok] (bf16, transposed)
        for (int i = tid; i < 4096; i += 256) {
            int tk = i >> 8, e4 = i & 255;
            float4 v = *(const float4*)(X + ((size_t)b * Nt + n0 + st * 16 + tk) * Dm + e4 * 4);
            unsigned p01 = bfpack(v.x, v.y);
            unsigned p23 = bfpack(v.z, v.w);
            fsh[e4 * 4 + 0][tk] = (unsigned short)(p01 & 0xffffu);
            fsh[e4 * 4 + 1][tk] = (unsigned short)(p01 >> 16);
            fsh[e4 * 4 + 2][tk] = (unsigned short)(p23 & 0xffffu);
            fsh[e4 * 4 + 3][tk] = (unsigned short)(p23 >> 16);
        }
        __syncthreads();
        unsigned a0 = *(const unsigned*)&ash[g][st * 16 + 2 * t];
        unsigned a1 = *(const unsigned*)&ash[g + 8][st * 16 + 2 * t];
        unsigned a2 = *(const unsigned*)&ash[g][st * 16 + 2 * t + 8];
        unsigned a3 = *(const unsigned*)&ash[g + 8][st * 16 + 2 * t + 8];
        #pragma unroll
        for (int nb = 0; nb < 16; nb++) {
            int e = w * 128 + nb * 8 + g;
            unsigned b0 = *(const unsigned*)&fsh[e][2 * t];
            unsigned b1 = *(const unsigned*)&fsh[e][2 * t + 8];
            MMA_BF16(c[nb], a0, a1, a2, a3, b0, b1);
        }
    }
    float* P = part + (((size_t)sp * Bsz + b) * Hh) * Dm;
    #pragma unroll
    for (int nb = 0; nb < 16; nb++) {
        int e = w * 128 + nb * 8 + 2 * t;
        P[(size_t)g * Dm + e]           = c[nb][0];
        P[(size_t)g * Dm + e + 1]       = c[nb][1];
        P[(size_t)(g + 8) * Dm + e]     = c[nb][2];
        P[(size_t)(g + 8) * Dm + e + 1] = c[nb][3];
    }
}

// ---------------- v-projection (fused split reduce) --------------------------
__global__ void k_vproj(const float* __restrict__ part, int NS,
                        const float* __restrict__ wv,
                        const float* __restrict__ bv, float* __restrict__ o)
{
    __shared__ float wsh[1024];
    int b = blockIdx.x, h = blockIdx.y, tid = threadIdx.x;
    float4 acc4 = make_float4(0.f, 0.f, 0.f, 0.f);
    for (int sp = 0; sp < NS; sp++) {
        float4 v = ((const float4*)(part + (((size_t)sp * Bsz + b) * Hh + h) * Dm))[tid];
        acc4.x += v.x; acc4.y += v.y; acc4.z += v.z; acc4.w += v.w;
    }
    ((float4*)wsh)[tid] = acc4;
    __syncthreads();
    int w = tid >> 5, lane = tid & 31;
    for (int dd = w; dd < 64; dd += 8) {
        int j = h * 64 + dd;
        const float4* wvp = (const float4*)(wv + (size_t)j * Dm);
        float acc = 0.f;
        #pragma unroll
        for (int i = 0; i < 8; i++) {
            float4 a = wvp[i * 32 + lane];
            float4 c = *(const float4*)&wsh[i * 128 + (lane << 2)];
            acc += a.x * c.x + a.y * c.y + a.z * c.z + a.w * c.w;
        }
        #pragma unroll
        for (int off = 16; off; off >>= 1) acc += __shfl_xor_sync(0xffffffffu, acc, off);
        if (lane == 0) o[(size_t)b * Dm + j] = acc + bv[j];
    }
}

// ---------------- host helper: split-K GEMM via partials ---------------------
static void gemm(const float* A, int lda, int M, const float* W, int N, int K,
                 int splitK, const float* bias, const float* Res, int ldr,
                 float* C, int ldc, int act, float* part)
{
    dim3 g(N / 64, splitK);
    k_gemm_part<<<g, 256>>>(A, lda, M, W, part, N, K, K / splitK);
    dim3 gr((N + 255) / 256, M);
    k_gemm_reduce<<<gr, 256>>>(part, C, ldc, bias, Res, ldr, M, N, splitK, act);
}

extern "C" void kernel_launch(void* const* d_in, const int* in_sizes, int n_in,
                              void* d_out, int out_size)
{
    const float* frame = (const float*)d_in[0];
    const float* kvs   = (const float*)d_in[1];
    const float* maxi  = (const float*)d_in[2];
    const float* qbase = (const float*)d_in[3];
    const float* role  = (const float*)d_in[4];
    const float* timew = (const float*)d_in[5];
    const float* ln1g  = (const float*)d_in[6];
    const float* ln1b  = (const float*)d_in[7];
    const float* sa_in_w = (const float*)d_in[8];
    const float* sa_in_b = (const float*)d_in[9];
    const float* sa_out_w = (const float*)d_in[10];
    const float* sa_out_b = (const float*)d_in[11];
    const float* ln2g  = (const float*)d_in[12];
    const float* ln2b  = (const float*)d_in[13];
    const float* cg_in_w = (const float*)d_in[14];
    const float* cg_in_b = (const float*)d_in[15];
    const float* cg_out_w = (const float*)d_in[16];
    const float* cg_out_b = (const float*)d_in[17];
    const float* cs_in_w = (const float*)d_in[18];
    const float* cs_in_b = (const float*)d_in[19];
    const float* cs_out_w = (const float*)d_in[20];
    const float* cs_out_b = (const float*)d_in[21];
    const float* ln3g  = (const float*)d_in[22];
    const float* ln3b  = (const float*)d_in[23];
    const float* fw1   = (const float*)d_in[24];
    const float* fb1   = (const float*)d_in[25];
    const float* fw2   = (const float*)d_in[26];
    const float* fb2   = (const float*)d_in[27];
    const float* outg  = (const float*)d_in[28];
    const float* outb  = (const float*)d_in[29];
    const int*   fidx  = (const int*)d_in[30];
    float* outp = (float*)d_out;

    void* sp_;
    cudaGetSymbolAddress(&sp_, g_scratch);
    float* S = (float*)sp_;
    float* mpart = S;                   // 524288
    float* q     = mpart + 524288;      // 65536
    float* x     = q + 65536;           // 65536
    float* t3    = x + 65536;           // 196608
    float* attn  = t3 + 196608;         // 65536
    float* qpg   = attn + 65536;        // 32768
    float* qps   = qpg + 32768;         // 32768
    float* ug    = qps + 32768;         // 524288
    float* us    = ug + 524288;         // 524288
    float* sg    = us + 524288;         // 2097152
    float* ss    = sg + 2097152;        // 524288
    float* wpart = ss + 524288;         // 8388608
    float* og    = wpart + 8388608;     // 32768
    float* os    = og + 32768;          // 32768
    float* gpart = os + 32768;          // 3276800
    float* hh    = gpart + 3276800;     // 262144

    // init: mean + q assembly
    k_mean_part<<<dim3(32, 16), 256>>>(frame, mpart);
    k_qinit<<<32, 256>>>(mpart, maxi, qbase, role, timew, fidx, q);

    for (int l = 0; l < 2; l++) {
        const float* l1g = ln1g + l * Dm;   const float* l1b = ln1b + l * Dm;
        const float* siw = sa_in_w + (size_t)l * 3072 * Dm;
        const float* sib = sa_in_b + l * 3072;
        const float* sow = sa_out_w + (size_t)l * Dm * Dm;
        const float* sob = sa_out_b + l * Dm;
        const float* l2g = ln2g + l * Dm;   const float* l2b = ln2b + l * Dm;
        const float* giw = cg_in_w + (size_t)l * 3072 * Dm;
        const float* gib = cg_in_b + l * 3072;
        const float* gow = cg_out_w + (size_t)l * Dm * Dm;
        const float* gob = cg_out_b + l * Dm;
        const float* ciw = cs_in_w + (size_t)l * 3072 * Dm;
        const float* cib = cs_in_b + l * 3072;
        const float* cow = cs_out_w + (size_t)l * Dm * Dm;
        const float* cob = cs_out_b + l * Dm;
        const float* l3g = ln3g + l * Dm;   const float* l3b = ln3b + l * Dm;
        const float* w1 = fw1 + (size_t)l * 4096 * Dm;
        const float* b1 = fb1 + l * 4096;
        const float* w2 = fw2 + (size_t)l * Dm * 4096;
        const float* b2 = fb2 + l * Dm;

        // ---- self-attention (2 tokens) ----
        k_ln<<<64, 256>>>(q, l1g, l1b, x);
        gemm(x, 1024, 64, siw, 3072, 1024, 16, sib, nullptr, 0, t3, 3072, 0, gpart);
        k_selfattn<<<dim3(32, 16), 64>>>(t3, attn);
        gemm(attn, 1024, 64, sow, 1024, 1024, 16, sob, q, 1024, q, 1024, 0, gpart);

        // ---- cross-attention (folded K/V) ----
        k_ln<<<64, 256>>>(q, l2g, l2b, x);
        gemm(x,        2048, 32, giw, 1024, 1024, 16, gib, nullptr, 0, qpg, 1024, 0, gpart);
        gemm(x + 1024, 2048, 32, ciw, 1024, 1024, 16, cib, nullptr, 0, qps, 1024, 0, gpart);
        k_ufold<<<dim3(16, 8), 128>>>(qpg, giw + 1024 * 1024, ug);
        k_ufold<<<dim3(16, 8), 128>>>(qps, ciw + 1024 * 1024, us);
        k_scores_mma<<<dim3(32, 32), 256>>>(frame, ug, sg, Nf);
        k_scores_mma<<<dim3(32, 8), 256>>>(kvs, us, ss, Kv);
        k_softmax<16><<<512, 256>>>(sg, Nf);
        k_softmax<4><<<512, 256>>>(ss, Kv);
        k_wbar_mma<<<dim3(32, 16), 256>>>(frame, sg, wpart, Nf);
        k_vproj<<<dim3(32, 16), 256>>>(wpart, 16, giw + 2 * 1024 * 1024, gib + 2048, og);
        k_wbar_mma<<<dim3(32, 4), 256>>>(kvs, ss, wpart, Kv);
        k_vproj<<<dim3(32, 16), 256>>>(wpart, 4, ciw + 2 * 1024 * 1024, cib + 2048, os);
        gemm(og, 1024, 32, gow, 1024, 1024, 16, gob, q,        2048, q,        2048, 0, gpart);
        gemm(os, 1024, 32, cow, 1024, 1024, 16, cob, q + 1024, 2048, q + 1024, 2048, 0, gpart);

        // ---- FFN ----
        k_ln<<<64, 256>>>(q, l3g, l3b, x);
        gemm(x, 1024, 64, w1, 4096, 1024, 8, b1, nullptr, 0, hh, 4096, 1, gpart);
        gemm(hh, 4096, 64, w2, 1024, 4096, 32, b2, q, 1024, q, 1024, 0, gpart);
    }

    // final LN -> d_out (B,2,D) contiguous
    k_ln<<<64, 256>>>(q, outg, outb, outp);
}

// round 13
// speedup vs baseline: 1.7687x; 1.0702x over previous
#include <cuda_runtime.h>
#include <math.h>

#define Bsz 32
#define Nf  4096
#define Kv  1024
#define Dm  1024
#define Hh  16
#define MAXF 4096

typedef unsigned long long u64;
typedef unsigned short u16;

// Static scratch — no allocations anywhere.
__device__ float g_scratch[16777216];          // 64 MB fp32 scratch
__device__ u16   g_frame_bf[134217728];        // 256 MB: frame as bf16
__device__ u16   g_kv_bf[33554432];            // 64 MB: kv_salient as bf16

// ---- f32x2 packed helpers ---------------------------------------------------
__device__ __forceinline__ void ffma2(u64& d, u64 a, u64 b)
{
    asm("fma.rn.f32x2 %0, %1, %2, %0;" : "+l"(d) : "l"(a), "l"(b));
}
__device__ __forceinline__ u64 dup2(float a)
{
    u64 r; asm("mov.b64 %0, {%1,%1};" : "=l"(r) : "f"(a)); return r;
}
// pack two fp32 -> bf16x2 (lo = first)
__device__ __forceinline__ unsigned bfpack(float lo, float hi)
{
    unsigned r;
    asm("cvt.rn.bf16x2.f32 %0, %1, %2;" : "=r"(r) : "f"(hi), "f"(lo));
    return r;
}
#define MMA_BF16(c, a0, a1, a2, a3, b0, b1) \
    asm("mma.sync.aligned.m16n8k16.row.col.f32.bf16.bf16.f32 " \
        "{%0,%1,%2,%3}, {%4,%5,%6,%7}, {%8,%9}, {%0,%1,%2,%3};" \
        : "+f"((c)[0]), "+f"((c)[1]), "+f"((c)[2]), "+f"((c)[3]) \
        : "r"(a0), "r"(a1), "r"(a2), "r"(a3), "r"(b0), "r"(b1))

// ---------------- mean over frame tokens + bf16 conversion -------------------
__global__ void k_mean_part(const float* __restrict__ frame, float* __restrict__ mpart,
                            u16* __restrict__ fbf)
{
    int b = blockIdx.x, sp = blockIdx.y, tid = threadIdx.x;
    size_t base = ((size_t)b * Nf + sp * 256) * Dm;
    const float4* fp = (const float4*)(frame + base) + tid;
    uint2* bp = (uint2*)(fbf + base) + tid;
    float4 acc = make_float4(0.f, 0.f, 0.f, 0.f);
    #pragma unroll 4
    for (int n = 0; n < 256; n++) {
        float4 v = fp[(size_t)n * 256];
        acc.x += v.x; acc.y += v.y; acc.z += v.z; acc.w += v.w;
        uint2 o; o.x = bfpack(v.x, v.y); o.y = bfpack(v.z, v.w);
        bp[(size_t)n * 256] = o;
    }
    ((float4*)(mpart + ((size_t)sp * Bsz + b) * Dm))[tid] = acc;
}

// ---------------- kv bf16 conversion -----------------------------------------
__global__ void k_cvt(const float* __restrict__ src, u16* __restrict__ dst)
{
    size_t i = ((size_t)blockIdx.x * 256 + threadIdx.x);
    const float4* s = (const float4*)src + i;
    uint2* d = (uint2*)dst + i;
    float4 v = *s;
    uint2 o; o.x = bfpack(v.x, v.y); o.y = bfpack(v.z, v.w);
    *d = o;
}

// ---------------- q init ------------------------------------------------------
__global__ void k_qinit(const float* __restrict__ mpart, const float* __restrict__ mi,
                        const float* __restrict__ qb, const float* __restrict__ role,
                        const float* __restrict__ tw, const int* __restrict__ fidx,
                        float* __restrict__ q)
{
    int b = blockIdx.x, tid = threadIdx.x;
    float4 m = make_float4(0.f, 0.f, 0.f, 0.f);
    for (int sp = 0; sp < 16; sp++) {
        float4 v = ((const float4*)(mpart + ((size_t)sp * Bsz + b) * Dm))[tid];
        m.x += v.x; m.y += v.y; m.z += v.z; m.w += v.w;
    }
    const float inv = 1.f / (float)Nf;
    int t = fidx[b]; t = t < 0 ? 0 : (t > MAXF - 1 ? MAXF - 1 : t);
    float4 te = ((const float4*)(tw + (size_t)t * Dm))[tid];
    float4 q0 = ((const float4*)qb)[tid];
    float4 q1 = ((const float4*)(qb + Dm))[tid];
    float4 r0 = ((const float4*)role)[tid];
    float4 r1 = ((const float4*)(role + Dm))[tid];
    float4 mv = ((const float4*)(mi + (size_t)b * Dm))[tid];
    float4 o0, o1;
    o0.x = m.x * inv + q0.x + r0.x + te.x;  o0.y = m.y * inv + q0.y + r0.y + te.y;
    o0.z = m.z * inv + q0.z + r0.z + te.z;  o0.w = m.w * inv + q0.w + r0.w + te.w;
    o1.x = mv.x + q1.x + r1.x + te.x;       o1.y = mv.y + q1.y + r1.y + te.y;
    o1.z = mv.z + q1.z + r1.z + te.z;       o1.w = mv.w + q1.w + r1.w + te.w;
    ((float4*)(q + (size_t)b * 2 * Dm))[tid] = o0;
    ((float4*)(q + (size_t)b * 2 * Dm + Dm))[tid] = o1;
}

// ---------------- LayerNorm ---------------------------------------------------
__global__ void k_ln(const float* __restrict__ in, const float* __restrict__ g,
                     const float* __restrict__ b, float* __restrict__ outp)
{
    __shared__ float2 red[256];
    int row = blockIdx.x, tid = threadIdx.x;
    float4 v = ((const float4*)(in + (size_t)row * Dm))[tid];
    float s = v.x + v.y + v.z + v.w;
    float sq = v.x * v.x + v.y * v.y + v.z * v.z + v.w * v.w;
    red[tid] = make_float2(s, sq); __syncthreads();
    for (int st = 128; st > 0; st >>= 1) {
        if (tid < st) { red[tid].x += red[tid + st].x; red[tid].y += red[tid + st].y; }
        __syncthreads();
    }
    float mean = red[0].x * (1.f / 1024.f);
    float var  = red[0].y * (1.f / 1024.f) - mean * mean;
    float rstd = rsqrtf(var + 1e-5f);
    float4 gv = ((const float4*)g)[tid];
    float4 bv = ((const float4*)b)[tid];
    float4 o;
    o.x = (v.x - mean) * rstd * gv.x + bv.x;
    o.y = (v.y - mean) * rstd * gv.y + bv.y;
    o.z = (v.z - mean) * rstd * gv.z + bv.z;
    o.w = (v.w - mean) * rstd * gv.w + bv.w;
    ((float4*)(outp + (size_t)row * Dm))[tid] = o;
}

// ---------------- small GEMM (measured-best R2 schedule) ---------------------
__global__ __launch_bounds__(256) void k_gemm_part(
    const float* __restrict__ A, int lda, int M,
    const float* __restrict__ W,
    float* __restrict__ part, int N, int K, int kchunk)
{
    __shared__ float As[16][64];
    __shared__ float Ws[16][64];
    int tid = threadIdx.x;
    int n0 = blockIdx.x * 64;
    int ks = blockIdx.y;
    int ty = tid >> 4, tx = tid & 15;
    int lm = tid >> 2;
    int lk = (tid & 3) << 2;
    u64 acc[4][2];
    #pragma unroll
    for (int i = 0; i < 4; i++) { acc[i][0] = 0ULL; acc[i][1] = 0ULL; }

    const float* Ap = A + (size_t)lm * lda;
    const float* Wp = W + (size_t)(n0 + lm) * K;
    int kend = ks * kchunk + kchunk;
    for (int kk = ks * kchunk; kk < kend; kk += 16) {
        float4 av = make_float4(0.f, 0.f, 0.f, 0.f);
        if (lm < M) av = *(const float4*)(Ap + kk + lk);
        float4 wv = *(const float4*)(Wp + kk + lk);
        __syncthreads();
        As[lk + 0][lm] = av.x; As[lk + 1][lm] = av.y; As[lk + 2][lm] = av.z; As[lk + 3][lm] = av.w;
        Ws[lk + 0][lm] = wv.x; Ws[lk + 1][lm] = wv.y; Ws[lk + 2][lm] = wv.z; Ws[lk + 3][lm] = wv.w;
        __syncthreads();
        #pragma unroll
        for (int k2 = 0; k2 < 16; k2++) {
            float4 a = *(const float4*)&As[k2][ty << 2];
            ulonglong2 w = *(const ulonglong2*)&Ws[k2][tx << 2];
            u64 d0 = dup2(a.x), d1 = dup2(a.y), d2 = dup2(a.z), d3 = dup2(a.w);
            ffma2(acc[0][0], d0, w.x); ffma2(acc[0][1], d0, w.y);
            ffma2(acc[1][0], d1, w.x); ffma2(acc[1][1], d1, w.y);
            ffma2(acc[2][0], d2, w.x); ffma2(acc[2][1], d2, w.y);
            ffma2(acc[3][0], d3, w.x); ffma2(acc[3][1], d3, w.y);
        }
    }
    float* P = part + (size_t)ks * M * N;
    #pragma unroll
    for (int i = 0; i < 4; i++) {
        int m = (ty << 2) + i;
        if (m < M) {
            ulonglong2* row = (ulonglong2*)(P + (size_t)m * N + n0 + (tx << 2));
            ulonglong2 v; v.x = acc[i][0]; v.y = acc[i][1];
            *row = v;
        }
    }
}

__device__ __forceinline__ float gelu_exact(float x)
{
    return 0.5f * x * (1.f + erff(x * 0.70710678118654752f));
}

__global__ void k_gemm_reduce(const float* __restrict__ part,
                              float* __restrict__ C, int ldc,
                              const float* __restrict__ bias,
                              const float* __restrict__ Res, int ldr,
                              int M, int N, int nsplit, int act)
{
    int n = blockIdx.x * 256 + threadIdx.x;
    int m = blockIdx.y;
    if (n >= N) return;
    float s = 0.f;
    for (int ks = 0; ks < nsplit; ks++) s += part[((size_t)ks * M + m) * N + n];
    s += bias[n];
    if (Res) s += Res[(size_t)m * ldr + n];
    if (act) s = gelu_exact(s);
    C[(size_t)m * ldc + n] = s;
}

// ---------------- 2-token self-attention core --------------------------------
__global__ void k_selfattn(const float* __restrict__ t3, float* __restrict__ attn)
{
    int b = blockIdx.x, h = blockIdx.y, d = threadIdx.x;
    const float* r0 = t3 + (size_t)(b * 2 + 0) * 3072;
    const float* r1 = t3 + (size_t)(b * 2 + 1) * 3072;
    int j = h * 64 + d;
    float q0 = r0[j], k0 = r0[1024 + j], v0 = r0[2048 + j];
    float q1 = r1[j], k1 = r1[1024 + j], v1 = r1[2048 + j];
    __shared__ float sh[4][64];
    sh[0][d] = q0 * k0; sh[1][d] = q0 * k1; sh[2][d] = q1 * k0; sh[3][d] = q1 * k1;
    __syncthreads();
    for (int st = 32; st > 0; st >>= 1) {
        if (d < st) {
            #pragma unroll
            for (int i = 0; i < 4; i++) sh[i][d] += sh[i][d + st];
        }
        __syncthreads();
    }
    float s00 = sh[0][0] * 0.125f, s01 = sh[1][0] * 0.125f;
    float s10 = sh[2][0] * 0.125f, s11 = sh[3][0] * 0.125f;
    float m0 = fmaxf(s00, s01), m1 = fmaxf(s10, s11);
    float e00 = expf(s00 - m0), e01 = expf(s01 - m0);
    float e10 = expf(s10 - m1), e11 = expf(s11 - m1);
    float a00 = e00 / (e00 + e01), a01 = e01 / (e00 + e01);
    float a10 = e10 / (e10 + e11), a11 = e11 / (e10 + e11);
    attn[(size_t)(b * 2 + 0) * Dm + j] = a00 * v0 + a01 * v1;
    attn[(size_t)(b * 2 + 1) * Dm + j] = a10 * v0 + a11 * v1;
}

// ---------------- fold: u[b,h,:] = qp[b, h*64: ] @ wk_h ----------------------
__global__ void k_ufold(const float* __restrict__ qp, const float* __restrict__ wk,
                        float* __restrict__ u)
{
    int h = blockIdx.x;
    int e = blockIdx.y * 128 + threadIdx.x;
    __shared__ float qs[32][64];
    for (int i = threadIdx.x; i < 2048; i += 128)
        qs[i >> 6][i & 63] = qp[(size_t)(i >> 6) * Dm + h * 64 + (i & 63)];
    __syncthreads();
    float acc[32];
    #pragma unroll
    for (int b2 = 0; b2 < 32; b2++) acc[b2] = 0.f;
    for (int d = 0; d < 64; d++) {
        float w = wk[(size_t)(h * 64 + d) * Dm + e];
        #pragma unroll
        for (int b2 = 0; b2 < 32; b2++) acc[b2] += qs[b2][d] * w;
    }
    #pragma unroll
    for (int b2 = 0; b2 < 32; b2++) u[((size_t)b2 * Hh + h) * Dm + e] = acc[b2];
}

// ---------------- scores via mma.sync bf16 (bf16 X source) -------------------
// s[b,h,n] = 0.125 * X[b,n,:] . u[b,h,:]
__global__ __launch_bounds__(256) void k_scores_mma(
    const u16* __restrict__ X, const float* __restrict__ u,
    float* __restrict__ s, int Nt)
{
    __shared__ u16 ush[16][1032];   // bf16 u, padded rows
    int b = blockIdx.x, tid = threadIdx.x;
    const float2* up = (const float2*)(u + (size_t)b * Hh * Dm);
    for (int i = tid; i < 8192; i += 256) {
        int h = i >> 9, d2 = i & 511;
        float2 v = up[(size_t)h * 512 + d2];
        *(unsigned*)&ush[h][d2 * 2] = bfpack(v.x, v.y);
    }
    __syncthreads();
    int w = tid >> 5, lane = tid & 31;
    int g = lane >> 2, t = lane & 3;
    int tok0 = (blockIdx.y * 8 + w) * 16;
    const u16* r0 = X + ((size_t)b * Nt + tok0 + g) * Dm + 2 * t;
    const u16* r1 = r0 + 8 * Dm;
    float c0[4] = {0.f, 0.f, 0.f, 0.f};
    float c1[4] = {0.f, 0.f, 0.f, 0.f};
    #pragma unroll 4
    for (int k0 = 0; k0 < 1024; k0 += 16) {
        unsigned a0 = *(const unsigned*)(r0 + k0);
        unsigned a1 = *(const unsigned*)(r1 + k0);
        unsigned a2 = *(const unsigned*)(r0 + k0 + 8);
        unsigned a3 = *(const unsigned*)(r1 + k0 + 8);
        unsigned b0 = *(const unsigned*)&ush[g][k0 + 2 * t];
        unsigned b1 = *(const unsigned*)&ush[g][k0 + 2 * t + 8];
        MMA_BF16(c0, a0, a1, a2, a3, b0, b1);
        unsigned b2 = *(const unsigned*)&ush[8 + g][k0 + 2 * t];
        unsigned b3 = *(const unsigned*)&ush[8 + g][k0 + 2 * t + 8];
        MMA_BF16(c1, a0, a1, a2, a3, b2, b3);
    }
    size_t sb = (size_t)b * Hh;
    const float sc = 0.125f;
    s[(sb + 2 * t    ) * Nt + tok0 + g    ] = c0[0] * sc;
    s[(sb + 2 * t + 1) * Nt + tok0 + g    ] = c0[1] * sc;
    s[(sb + 2 * t    ) * Nt + tok0 + g + 8] = c0[2] * sc;
    s[(sb + 2 * t + 1) * Nt + tok0 + g + 8] = c0[3] * sc;
    s[(sb + 8 + 2 * t    ) * Nt + tok0 + g    ] = c1[0] * sc;
    s[(sb + 8 + 2 * t + 1) * Nt + tok0 + g    ] = c1[1] * sc;
    s[(sb + 8 + 2 * t    ) * Nt + tok0 + g + 8] = c1[2] * sc;
    s[(sb + 8 + 2 * t + 1) * Nt + tok0 + g + 8] = c1[3] * sc;
}

// ---------------- row softmax over Nt ----------------------------------------
template <int CNT>
__global__ void k_softmax(float* __restrict__ s, int Nt)
{
    __shared__ float red[256];
    size_t base = (size_t)blockIdx.x * Nt;
    int tid = threadIdx.x;
    float v[CNT];
    float mx = -1e30f;
    #pragma unroll
    for (int i = 0; i < CNT; i++) { v[i] = s[base + i * 256 + tid]; mx = fmaxf(mx, v[i]); }
    red[tid] = mx; __syncthreads();
    for (int st = 128; st > 0; st >>= 1) {
        if (tid < st) red[tid] = fmaxf(red[tid], red[tid + st]);
        __syncthreads();
    }
    mx = red[0]; __syncthreads();
    float sum = 0.f;
    #pragma unroll
    for (int i = 0; i < CNT; i++) { v[i] = expf(v[i] - mx); sum += v[i]; }
    red[tid] = sum; __syncthreads();
    for (int st = 128; st > 0; st >>= 1) {
        if (tid < st) red[tid] += red[tid + st];
        __syncthreads();
    }
    float inv = 1.f / red[0];
    #pragma unroll
    for (int i = 0; i < CNT; i++) s[base + i * 256 + tid] = v[i] * inv;
}

// ---------------- wbar via mma.sync bf16 (bf16 X source) ---------------------
__global__ __launch_bounds__(256) void k_wbar_mma(
    const u16* __restrict__ X, const float* __restrict__ a,
    float* __restrict__ part, int Nt)
{
    __shared__ u16 ash[16][264];    // att weights bf16 [h][tok]
    __shared__ u16 fsh[1024][18];   // frame^T bf16 [e][tok16]
    int b = blockIdx.x, sp = blockIdx.y, tid = threadIdx.x;
    int n0 = sp * 256;
    for (int i = tid; i < 2048; i += 256) {
        int h = i >> 7, t2 = i & 127;
        float2 v = *(const float2*)(a + ((size_t)b * Hh + h) * Nt + n0 + t2 * 2);
        *(unsigned*)&ash[h][t2 * 2] = bfpack(v.x, v.y);
    }
    int w = tid >> 5, lane = tid & 31;
    int g = lane >> 2, t = lane & 3;
    float c[16][4];
    #pragma unroll
    for (int nb = 0; nb < 16; nb++) {
        c[nb][0] = 0.f; c[nb][1] = 0.f; c[nb][2] = 0.f; c[nb][3] = 0.f;
    }

    for (int st = 0; st < 16; st++) {
        __syncthreads();
        // stage X[16 tok][1024 e] (bf16) -> fsh[e][tok] transposed
        for (int i = tid; i < 4096; i += 256) {
            int tk = i >> 8, e4 = i & 255;
            uint2 v = *(const uint2*)(X + ((size_t)b * Nt + n0 + st * 16 + tk) * Dm + e4 * 4);
            fsh[e4 * 4 + 0][tk] = (u16)(v.x & 0xffffu);
            fsh[e4 * 4 + 1][tk] = (u16)(v.x >> 16);
            fsh[e4 * 4 + 2][tk] = (u16)(v.y & 0xffffu);
            fsh[e4 * 4 + 3][tk] = (u16)(v.y >> 16);
        }
        __syncthreads();
        unsigned a0 = *(const unsigned*)&ash[g][st * 16 + 2 * t];
        unsigned a1 = *(const unsigned*)&ash[g + 8][st * 16 + 2 * t];
        unsigned a2 = *(const unsigned*)&ash[g][st * 16 + 2 * t + 8];
        unsigned a3 = *(const unsigned*)&ash[g + 8][st * 16 + 2 * t + 8];
        #pragma unroll
        for (int nb = 0; nb < 16; nb++) {
            int e = w * 128 + nb * 8 + g;
            unsigned b0 = *(const unsigned*)&fsh[e][2 * t];
            unsigned b1 = *(const unsigned*)&fsh[e][2 * t + 8];
            MMA_BF16(c[nb], a0, a1, a2, a3, b0, b1);
        }
    }
    float* P = part + (((size_t)sp * Bsz + b) * Hh) * Dm;
    #pragma unroll
    for (int nb = 0; nb < 16; nb++) {
        int e = w * 128 + nb * 8 + 2 * t;
        P[(size_t)g * Dm + e]           = c[nb][0];
        P[(size_t)g * Dm + e + 1]       = c[nb][1];
        P[(size_t)(g + 8) * Dm + e]     = c[nb][2];
        P[(size_t)(g + 8) * Dm + e + 1] = c[nb][3];
    }
}

// ---------------- v-projection (fused split reduce) --------------------------
__global__ void k_vproj(const float* __restrict__ part, int NS,
                        const float* __restrict__ wv,
                        const float* __restrict__ bv, float* __restrict__ o)
{
    __shared__ float wsh[1024];
    int b = blockIdx.x, h = blockIdx.y, tid = threadIdx.x;
    float4 acc4 = make_float4(0.f, 0.f, 0.f, 0.f);
    for (int sp = 0; sp < NS; sp++) {
        float4 v = ((const float4*)(part + (((size_t)sp * Bsz + b) * Hh + h) * Dm))[tid];
        acc4.x += v.x; acc4.y += v.y; acc4.z += v.z; acc4.w += v.w;
    }
    ((float4*)wsh)[tid] = acc4;
    __syncthreads();
    int w = tid >> 5, lane = tid & 31;
    for (int dd = w; dd < 64; dd += 8) {
        int j = h * 64 + dd;
        const float4* wvp = (const float4*)(wv + (size_t)j * Dm);
        float acc = 0.f;
        #pragma unroll
        for (int i = 0; i < 8; i++) {
            float4 a = wvp[i * 32 + lane];
            float4 c = *(const float4*)&wsh[i * 128 + (lane << 2)];
            acc += a.x * c.x + a.y * c.y + a.z * c.z + a.w * c.w;
        }
        #pragma unroll
        for (int off = 16; off; off >>= 1) acc += __shfl_xor_sync(0xffffffffu, acc, off);
        if (lane == 0) o[(size_t)b * Dm + j] = acc + bv[j];
    }
}

// ---------------- host helper: split-K GEMM via partials ---------------------
static void gemm(const float* A, int lda, int M, const float* W, int N, int K,
                 int splitK, const float* bias, const float* Res, int ldr,
                 float* C, int ldc, int act, float* part)
{
    dim3 g(N / 64, splitK);
    k_gemm_part<<<g, 256>>>(A, lda, M, W, part, N, K, K / splitK);
    dim3 gr((N + 255) / 256, M);
    k_gemm_reduce<<<gr, 256>>>(part, C, ldc, bias, Res, ldr, M, N, splitK, act);
}

extern "C" void kernel_launch(void* const* d_in, const int* in_sizes, int n_in,
                              void* d_out, int out_size)
{
    const float* frame = (const float*)d_in[0];
    const float* kvs   = (const float*)d_in[1];
    const float* maxi  = (const float*)d_in[2];
    const float* qbase = (const float*)d_in[3];
    const float* role  = (const float*)d_in[4];
    const float* timew = (const float*)d_in[5];
    const float* ln1g  = (const float*)d_in[6];
    const float* ln1b  = (const float*)d_in[7];
    const float* sa_in_w = (const float*)d_in[8];
    const float* sa_in_b = (const float*)d_in[9];
    const float* sa_out_w = (const float*)d_in[10];
    const float* sa_out_b = (const float*)d_in[11];
    const float* ln2g  = (const float*)d_in[12];
    const float* ln2b  = (const float*)d_in[13];
    const float* cg_in_w = (const float*)d_in[14];
    const float* cg_in_b = (const float*)d_in[15];
    const float* cg_out_w = (const float*)d_in[16];
    const float* cg_out_b = (const float*)d_in[17];
    const float* cs_in_w = (const float*)d_in[18];
    const float* cs_in_b = (const float*)d_in[19];
    const float* cs_out_w = (const float*)d_in[20];
    const float* cs_out_b = (const float*)d_in[21];
    const float* ln3g  = (const float*)d_in[22];
    const float* ln3b  = (const float*)d_in[23];
    const float* fw1   = (const float*)d_in[24];
    const float* fb1   = (const float*)d_in[25];
    const float* fw2   = (const float*)d_in[26];
    const float* fb2   = (const float*)d_in[27];
    const float* outg  = (const float*)d_in[28];
    const float* outb  = (const float*)d_in[29];
    const int*   fidx  = (const int*)d_in[30];
    float* outp = (float*)d_out;

    void* sp_;
    cudaGetSymbolAddress(&sp_, g_scratch);
    float* S = (float*)sp_;
    void* fb_; cudaGetSymbolAddress(&fb_, g_frame_bf);
    u16* framebf = (u16*)fb_;
    void* kb_; cudaGetSymbolAddress(&kb_, g_kv_bf);
    u16* kvbf = (u16*)kb_;

    float* mpart = S;                   // 524288
    float* q     = mpart + 524288;      // 65536
    float* x     = q + 65536;           // 65536
    float* t3    = x + 65536;           // 196608
    float* attn  = t3 + 196608;         // 65536
    float* qpg   = attn + 65536;        // 32768
    float* qps   = qpg + 32768;         // 32768
    float* ug    = qps + 32768;         // 524288
    float* us    = ug + 524288;         // 524288
    float* sg    = us + 524288;         // 2097152
    float* ss    = sg + 2097152;        // 524288
    float* wpart = ss + 524288;         // 8388608
    float* og    = wpart + 8388608;     // 32768
    float* os    = og + 32768;          // 32768
    float* gpart = os + 32768;          // 3276800
    float* hh    = gpart + 3276800;     // 262144

    // init: mean + bf16 conversion + q assembly
    k_mean_part<<<dim3(32, 16), 256>>>(frame, mpart, framebf);
    k_cvt<<<32768, 256>>>(kvs, kvbf);
    k_qinit<<<32, 256>>>(mpart, maxi, qbase, role, timew, fidx, q);

    for (int l = 0; l < 2; l++) {
        const float* l1g = ln1g + l * Dm;   const float* l1b = ln1b + l * Dm;
        const float* siw = sa_in_w + (size_t)l * 3072 * Dm;
        const float* sib = sa_in_b + l * 3072;
        const float* sow = sa_out_w + (size_t)l * Dm * Dm;
        const float* sob = sa_out_b + l * Dm;
        const float* l2g = ln2g + l * Dm;   const float* l2b = ln2b + l * Dm;
        const float* giw = cg_in_w + (size_t)l * 3072 * Dm;
        const float* gib = cg_in_b + l * 3072;
        const float* gow = cg_out_w + (size_t)l * Dm * Dm;
        const float* gob = cg_out_b + l * Dm;
        const float* ciw = cs_in_w + (size_t)l * 3072 * Dm;
        const float* cib = cs_in_b + l * 3072;
        const float* cow = cs_out_w + (size_t)l * Dm * Dm;
        const float* cob = cs_out_b + l * Dm;
        const float* l3g = ln3g + l * Dm;   const float* l3b = ln3b + l * Dm;
        const float* w1 = fw1 + (size_t)l * 4096 * Dm;
        const float* b1 = fb1 + l * 4096;
        const float* w2 = fw2 + (size_t)l * Dm * 4096;
        const float* b2 = fb2 + l * Dm;

        // ---- self-attention (2 tokens) ----
        k_ln<<<64, 256>>>(q, l1g, l1b, x);
        gemm(x, 1024, 64, siw, 3072, 1024, 16, sib, nullptr, 0, t3, 3072, 0, gpart);
        k_selfattn<<<dim3(32, 16), 64>>>(t3, attn);
        gemm(attn, 1024, 64, sow, 1024, 1024, 16, sob, q, 1024, q, 1024, 0, gpart);

        // ---- cross-attention (folded K/V) ----
        k_ln<<<64, 256>>>(q, l2g, l2b, x);
        gemm(x,        2048, 32, giw, 1024, 1024, 16, gib, nullptr, 0, qpg, 1024, 0, gpart);
        gemm(x + 1024, 2048, 32, ciw, 1024, 1024, 16, cib, nullptr, 0, qps, 1024, 0, gpart);
        k_ufold<<<dim3(16, 8), 128>>>(qpg, giw + 1024 * 1024, ug);
        k_ufold<<<dim3(16, 8), 128>>>(qps, ciw + 1024 * 1024, us);
        k_scores_mma<<<dim3(32, 32), 256>>>(framebf, ug, sg, Nf);
        k_scores_mma<<<dim3(32, 8), 256>>>(kvbf, us, ss, Kv);
        k_softmax<16><<<512, 256>>>(sg, Nf);
        k_softmax<4><<<512, 256>>>(ss, Kv);
        k_wbar_mma<<<dim3(32, 16), 256>>>(framebf, sg, wpart, Nf);
        k_vproj<<<dim3(32, 16), 256>>>(wpart, 16, giw + 2 * 1024 * 1024, gib + 2048, og);
        k_wbar_mma<<<dim3(32, 4), 256>>>(kvbf, ss, wpart, Kv);
        k_vproj<<<dim3(32, 16), 256>>>(wpart, 4, ciw + 2 * 1024 * 1024, cib + 2048, os);
        gemm(og, 1024, 32, gow, 1024, 1024, 16, gob, q,        2048, q,        2048, 0, gpart);
        gemm(os, 1024, 32, cow, 1024, 1024, 16, cob, q + 1024, 2048, q + 1024, 2048, 0, gpart);

        // ---- FFN ----
        k_ln<<<64, 256>>>(q, l3g, l3b, x);
        gemm(x, 1024, 64, w1, 4096, 1024, 8, b1, nullptr, 0, hh, 4096, 1, gpart);
        gemm(hh, 4096, 64, w2, 1024, 4096, 32, b2, q, 1024, q, 1024, 0, gpart);
    }

    // final LN -> d_out (B,2,D) contiguous
    k_ln<<<64, 256>>>(q, outg, outb, outp);
}

// round 14
// speedup vs baseline: 1.7973x; 1.0162x over previous
#include <cuda_runtime.h>
#include <math.h>

#define Bsz 32
#define Nf  4096
#define Kv  1024
#define Dm  1024
#define Hh  16
#define MAXF 4096
#define WKV_OFF 8388608

typedef unsigned long long u64;
typedef unsigned short u16;

// Static scratch — no allocations anywhere.
__device__ float g_scratch[16777216];          // 64 MB fp32 scratch
__device__ u16   g_frame_bf[134217728];        // 256 MB: frame as bf16
__device__ u16   g_kv_bf[33554432];            // 64 MB: kv_salient as bf16

// ---- packed helpers ---------------------------------------------------------
__device__ __forceinline__ void ffma2(u64& d, u64 a, u64 b)
{
    asm("fma.rn.f32x2 %0, %1, %2, %0;" : "+l"(d) : "l"(a), "l"(b));
}
__device__ __forceinline__ u64 dup2(float a)
{
    u64 r; asm("mov.b64 %0, {%1,%1};" : "=l"(r) : "f"(a)); return r;
}
// pack two fp32 -> bf16x2 (lo = first arg in low 16 bits)
__device__ __forceinline__ unsigned bfpack(float lo, float hi)
{
    unsigned r;
    asm("cvt.rn.bf16x2.f32 %0, %1, %2;" : "=r"(r) : "f"(hi), "f"(lo));
    return r;
}
#define MMA_BF16(c, a0, a1, a2, a3, b0, b1) \
    asm("mma.sync.aligned.m16n8k16.row.col.f32.bf16.bf16.f32 " \
        "{%0,%1,%2,%3}, {%4,%5,%6,%7}, {%8,%9}, {%0,%1,%2,%3};" \
        : "+f"((c)[0]), "+f"((c)[1]), "+f"((c)[2]), "+f"((c)[3]) \
        : "r"(a0), "r"(a1), "r"(a2), "r"(a3), "r"(b0), "r"(b1))

// ---------------- mean over frame tokens + bf16 conversion -------------------
__global__ void k_mean_part(const float* __restrict__ frame, float* __restrict__ mpart,
                            u16* __restrict__ fbf)
{
    int b = blockIdx.x, sp = blockIdx.y, tid = threadIdx.x;
    size_t base = ((size_t)b * Nf + sp * 256) * Dm;
    const float4* fp = (const float4*)(frame + base) + tid;
    uint2* bp = (uint2*)(fbf + base) + tid;
    float4 acc = make_float4(0.f, 0.f, 0.f, 0.f);
    #pragma unroll 4
    for (int n = 0; n < 256; n++) {
        float4 v = fp[(size_t)n * 256];
        acc.x += v.x; acc.y += v.y; acc.z += v.z; acc.w += v.w;
        uint2 o; o.x = bfpack(v.x, v.y); o.y = bfpack(v.z, v.w);
        bp[(size_t)n * 256] = o;
    }
    ((float4*)(mpart + ((size_t)sp * Bsz + b) * Dm))[tid] = acc;
}

// ---------------- kv bf16 conversion -----------------------------------------
__global__ void k_cvt(const float* __restrict__ src, u16* __restrict__ dst)
{
    size_t i = ((size_t)blockIdx.x * 256 + threadIdx.x);
    float4 v = ((const float4*)src)[i];
    uint2 o; o.x = bfpack(v.x, v.y); o.y = bfpack(v.z, v.w);
    ((uint2*)dst)[i] = o;
}

// ---------------- q init ------------------------------------------------------
__global__ void k_qinit(const float* __restrict__ mpart, const float* __restrict__ mi,
                        const float* __restrict__ qb, const float* __restrict__ role,
                        const float* __restrict__ tw, const int* __restrict__ fidx,
                        float* __restrict__ q)
{
    int b = blockIdx.x, tid = threadIdx.x;
    float4 m = make_float4(0.f, 0.f, 0.f, 0.f);
    for (int sp = 0; sp < 16; sp++) {
        float4 v = ((const float4*)(mpart + ((size_t)sp * Bsz + b) * Dm))[tid];
        m.x += v.x; m.y += v.y; m.z += v.z; m.w += v.w;
    }
    const float inv = 1.f / (float)Nf;
    int t = fidx[b]; t = t < 0 ? 0 : (t > MAXF - 1 ? MAXF - 1 : t);
    float4 te = ((const float4*)(tw + (size_t)t * Dm))[tid];
    float4 q0 = ((const float4*)qb)[tid];
    float4 q1 = ((const float4*)(qb + Dm))[tid];
    float4 r0 = ((const float4*)role)[tid];
    float4 r1 = ((const float4*)(role + Dm))[tid];
    float4 mv = ((const float4*)(mi + (size_t)b * Dm))[tid];
    float4 o0, o1;
    o0.x = m.x * inv + q0.x + r0.x + te.x;  o0.y = m.y * inv + q0.y + r0.y + te.y;
    o0.z = m.z * inv + q0.z + r0.z + te.z;  o0.w = m.w * inv + q0.w + r0.w + te.w;
    o1.x = mv.x + q1.x + r1.x + te.x;       o1.y = mv.y + q1.y + r1.y + te.y;
    o1.z = mv.z + q1.z + r1.z + te.z;       o1.w = mv.w + q1.w + r1.w + te.w;
    ((float4*)(q + (size_t)b * 2 * Dm))[tid] = o0;
    ((float4*)(q + (size_t)b * 2 * Dm + Dm))[tid] = o1;
}

// ---------------- LayerNorm ---------------------------------------------------
__global__ void k_ln(const float* __restrict__ in, const float* __restrict__ g,
                     const float* __restrict__ b, float* __restrict__ outp)
{
    __shared__ float2 red[256];
    int row = blockIdx.x, tid = threadIdx.x;
    float4 v = ((const float4*)(in + (size_t)row * Dm))[tid];
    float s = v.x + v.y + v.z + v.w;
    float sq = v.x * v.x + v.y * v.y + v.z * v.z + v.w * v.w;
    red[tid] = make_float2(s, sq); __syncthreads();
    for (int st = 128; st > 0; st >>= 1) {
        if (tid < st) { red[tid].x += red[tid + st].x; red[tid].y += red[tid + st].y; }
        __syncthreads();
    }
    float mean = red[0].x * (1.f / 1024.f);
    float var  = red[0].y * (1.f / 1024.f) - mean * mean;
    float rstd = rsqrtf(var + 1e-5f);
    float4 gv = ((const float4*)g)[tid];
    float4 bv = ((const float4*)b)[tid];
    float4 o;
    o.x = (v.x - mean) * rstd * gv.x + bv.x;
    o.y = (v.y - mean) * rstd * gv.y + bv.y;
    o.z = (v.z - mean) * rstd * gv.z + bv.z;
    o.w = (v.w - mean) * rstd * gv.w + bv.w;
    ((float4*)(outp + (size_t)row * Dm))[tid] = o;
}

// ---------------- small GEMM (measured-best R2 schedule) ---------------------
__global__ __launch_bounds__(256) void k_gemm_part(
    const float* __restrict__ A, int lda, int M,
    const float* __restrict__ W,
    float* __restrict__ part, int N, int K, int kchunk)
{
    __shared__ float As[16][64];
    __shared__ float Ws[16][64];
    int tid = threadIdx.x;
    int n0 = blockIdx.x * 64;
    int ks = blockIdx.y;
    int ty = tid >> 4, tx = tid & 15;
    int lm = tid >> 2;
    int lk = (tid & 3) << 2;
    u64 acc[4][2];
    #pragma unroll
    for (int i = 0; i < 4; i++) { acc[i][0] = 0ULL; acc[i][1] = 0ULL; }

    const float* Ap = A + (size_t)lm * lda;
    const float* Wp = W + (size_t)(n0 + lm) * K;
    int kend = ks * kchunk + kchunk;
    for (int kk = ks * kchunk; kk < kend; kk += 16) {
        float4 av = make_float4(0.f, 0.f, 0.f, 0.f);
        if (lm < M) av = *(const float4*)(Ap + kk + lk);
        float4 wv = *(const float4*)(Wp + kk + lk);
        __syncthreads();
        As[lk + 0][lm] = av.x; As[lk + 1][lm] = av.y; As[lk + 2][lm] = av.z; As[lk + 3][lm] = av.w;
        Ws[lk + 0][lm] = wv.x; Ws[lk + 1][lm] = wv.y; Ws[lk + 2][lm] = wv.z; Ws[lk + 3][lm] = wv.w;
        __syncthreads();
        #pragma unroll
        for (int k2 = 0; k2 < 16; k2++) {
            float4 a = *(const float4*)&As[k2][ty << 2];
            ulonglong2 w = *(const ulonglong2*)&Ws[k2][tx << 2];
            u64 d0 = dup2(a.x), d1 = dup2(a.y), d2 = dup2(a.z), d3 = dup2(a.w);
            ffma2(acc[0][0], d0, w.x); ffma2(acc[0][1], d0, w.y);
            ffma2(acc[1][0], d1, w.x); ffma2(acc[1][1], d1, w.y);
            ffma2(acc[2][0], d2, w.x); ffma2(acc[2][1], d2, w.y);
            ffma2(acc[3][0], d3, w.x); ffma2(acc[3][1], d3, w.y);
        }
    }
    float* P = part + (size_t)ks * M * N;
    #pragma unroll
    for (int i = 0; i < 4; i++) {
        int m = (ty << 2) + i;
        if (m < M) {
            ulonglong2* row = (ulonglong2*)(P + (size_t)m * N + n0 + (tx << 2));
            ulonglong2 v; v.x = acc[i][0]; v.y = acc[i][1];
            *row = v;
        }
    }
}

__device__ __forceinline__ float gelu_exact(float x)
{
    return 0.5f * x * (1.f + erff(x * 0.70710678118654752f));
}

__global__ void k_gemm_reduce(const float* __restrict__ part,
                              float* __restrict__ C, int ldc,
                              const float* __restrict__ bias,
                              const float* __restrict__ Res, int ldr,
                              int M, int N, int nsplit, int act)
{
    int n = blockIdx.x * 256 + threadIdx.x;
    int m = blockIdx.y;
    if (n >= N) return;
    float s = 0.f;
    for (int ks = 0; ks < nsplit; ks++) s += part[((size_t)ks * M + m) * N + n];
    s += bias[n];
    if (Res) s += Res[(size_t)m * ldr + n];
    if (act) s = gelu_exact(s);
    C[(size_t)m * ldc + n] = s;
}

// ---------------- 2-token self-attention core --------------------------------
__global__ void k_selfattn(const float* __restrict__ t3, float* __restrict__ attn)
{
    int b = blockIdx.x, h = blockIdx.y, d = threadIdx.x;
    const float* r0 = t3 + (size_t)(b * 2 + 0) * 3072;
    const float* r1 = t3 + (size_t)(b * 2 + 1) * 3072;
    int j = h * 64 + d;
    float q0 = r0[j], k0 = r0[1024 + j], v0 = r0[2048 + j];
    float q1 = r1[j], k1 = r1[1024 + j], v1 = r1[2048 + j];
    __shared__ float sh[4][64];
    sh[0][d] = q0 * k0; sh[1][d] = q0 * k1; sh[2][d] = q1 * k0; sh[3][d] = q1 * k1;
    __syncthreads();
    for (int st = 32; st > 0; st >>= 1) {
        if (d < st) {
            #pragma unroll
            for (int i = 0; i < 4; i++) sh[i][d] += sh[i][d + st];
        }
        __syncthreads();
    }
    float s00 = sh[0][0] * 0.125f, s01 = sh[1][0] * 0.125f;
    float s10 = sh[2][0] * 0.125f, s11 = sh[3][0] * 0.125f;
    float m0 = fmaxf(s00, s01), m1 = fmaxf(s10, s11);
    float e00 = expf(s00 - m0), e01 = expf(s01 - m0);
    float e10 = expf(s10 - m1), e11 = expf(s11 - m1);
    float a00 = e00 / (e00 + e01), a01 = e01 / (e00 + e01);
    float a10 = e10 / (e10 + e11), a11 = e11 / (e10 + e11);
    attn[(size_t)(b * 2 + 0) * Dm + j] = a00 * v0 + a01 * v1;
    attn[(size_t)(b * 2 + 1) * Dm + j] = a10 * v0 + a11 * v1;
}

// ---------------- fold: u[b,h,:] = qp[b, h*64: ] @ wk_h ----------------------
__global__ void k_ufold(const float* __restrict__ qp, const float* __restrict__ wk,
                        float* __restrict__ u)
{
    int h = blockIdx.x;
    int e = blockIdx.y * 128 + threadIdx.x;
    __shared__ float qs[32][64];
    for (int i = threadIdx.x; i < 2048; i += 128)
        qs[i >> 6][i & 63] = qp[(size_t)(i >> 6) * Dm + h * 64 + (i & 63)];
    __syncthreads();
    float acc[32];
    #pragma unroll
    for (int b2 = 0; b2 < 32; b2++) acc[b2] = 0.f;
    for (int d = 0; d < 64; d++) {
        float w = wk[(size_t)(h * 64 + d) * Dm + e];
        #pragma unroll
        for (int b2 = 0; b2 < 32; b2++) acc[b2] += qs[b2][d] * w;
    }
    #pragma unroll
    for (int b2 = 0; b2 < 32; b2++) u[((size_t)b2 * Hh + h) * Dm + e] = acc[b2];
}

// ---------------- fused flash attention: scores+softmax+wbar -----------------
// One pass over X per layer. Per (b, chunk): 16 stages of 16 tokens.
// Outputs per chunk: unnormalized wbar partial (local-max frame) + (m, s) stats.
__global__ __launch_bounds__(256) void k_attn(
    const u16* __restrict__ Xf, const u16* __restrict__ Xk,
    const float* __restrict__ ug, const float* __restrict__ us,
    float* __restrict__ wpart, float* __restrict__ stm, float* __restrict__ sts)
{
    extern __shared__ char shm[];
    u16 (*ush)[1032]  = (u16(*)[1032])shm;                                // 33024 B
    u16 (*fsh)[18]    = (u16(*)[18])(shm + 33024);                        // 36864 B
    float (*swarp)[16][17] = (float(*)[16][17])(shm + 33024 + 36864);     // 8704 B
    u16 (*ashs)[24]   = (u16(*)[24])(shm + 33024 + 36864 + 8704);         // 768 B
    float* mrun = (float*)(shm + 33024 + 36864 + 8704 + 768);             // 64 B
    float* srun = mrun + 16;
    float* fh   = srun + 16;

    int b = blockIdx.x, sp = blockIdx.y, tid = threadIdx.x;
    const u16* X; const float* u; int Nt, n0; float* dst;
    if (sp < 16) {
        X = Xf; u = ug; Nt = Nf; n0 = sp * 256;
        dst = wpart + ((size_t)sp * Bsz + b) * (Hh * Dm);
    } else {
        int k2 = sp - 16;
        X = Xk; u = us; Nt = Kv; n0 = k2 * 256;
        dst = wpart + WKV_OFF + ((size_t)k2 * Bsz + b) * (Hh * Dm);
    }
    // stage u (fp32 -> bf16 shared)
    const float2* up = (const float2*)(u + (size_t)b * Hh * Dm);
    for (int i = tid; i < 8192; i += 256) {
        int h = i >> 9, d2 = i & 511;
        float2 v = up[(size_t)h * 512 + d2];
        *(unsigned*)&ush[h][d2 * 2] = bfpack(v.x, v.y);
    }
    if (tid < 16) { mrun[tid] = -3e38f; srun[tid] = 0.f; }

    int w = tid >> 5, lane = tid & 31;
    int g = lane >> 2, t = lane & 3;
    int hh_ = tid >> 4, tk_ = tid & 15;     // softmax role: (head, token)
    float c[16][4];
    #pragma unroll
    for (int nb = 0; nb < 16; nb++) {
        c[nb][0] = 0.f; c[nb][1] = 0.f; c[nb][2] = 0.f; c[nb][3] = 0.f;
    }

    for (int st = 0; st < 16; st++) {
        __syncthreads();
        // stage X[16 tok][1024 e] (bf16) -> fsh[e][tok]
        for (int i = tid; i < 4096; i += 256) {
            int tk = i >> 8, e4 = i & 255;
            uint2 v = *(const uint2*)(X + ((size_t)b * Nt + n0 + st * 16 + tk) * Dm + e4 * 4);
            fsh[e4 * 4 + 0][tk] = (u16)(v.x & 0xffffu);
            fsh[e4 * 4 + 1][tk] = (u16)(v.x >> 16);
            fsh[e4 * 4 + 2][tk] = (u16)(v.y & 0xffffu);
            fsh[e4 * 4 + 3][tk] = (u16)(v.y >> 16);
        }
        __syncthreads();
        // --- scores: warp w covers k slice [w*128, w*128+128) ---
        {
            int kw = w * 128;
            float c0[4] = {0.f, 0.f, 0.f, 0.f};
            float c1[4] = {0.f, 0.f, 0.f, 0.f};
            const u16* r0 = X + ((size_t)b * Nt + n0 + st * 16 + g) * Dm + kw + 2 * t;
            const u16* r1 = r0 + 8 * Dm;
            #pragma unroll
            for (int k0 = 0; k0 < 128; k0 += 16) {
                unsigned a0 = *(const unsigned*)(r0 + k0);
                unsigned a1 = *(const unsigned*)(r1 + k0);
                unsigned a2 = *(const unsigned*)(r0 + k0 + 8);
                unsigned a3 = *(const unsigned*)(r1 + k0 + 8);
                unsigned b0 = *(const unsigned*)&ush[g][kw + k0 + 2 * t];
                unsigned b1 = *(const unsigned*)&ush[g][kw + k0 + 2 * t + 8];
                MMA_BF16(c0, a0, a1, a2, a3, b0, b1);
                unsigned b2 = *(const unsigned*)&ush[8 + g][kw + k0 + 2 * t];
                unsigned b3 = *(const unsigned*)&ush[8 + g][kw + k0 + 2 * t + 8];
                MMA_BF16(c1, a0, a1, a2, a3, b2, b3);
            }
            // same result mapping as proven k_scores_mma: (head, token)
            swarp[w][2 * t    ][g    ] = c0[0];
            swarp[w][2 * t + 1][g    ] = c0[1];
            swarp[w][2 * t    ][g + 8] = c0[2];
            swarp[w][2 * t + 1][g + 8] = c0[3];
            swarp[w][8 + 2 * t    ][g    ] = c1[0];
            swarp[w][8 + 2 * t + 1][g    ] = c1[1];
            swarp[w][8 + 2 * t    ][g + 8] = c1[2];
            swarp[w][8 + 2 * t + 1][g + 8] = c1[3];
        }
        __syncthreads();
        // --- online softmax update: thread = (head hh_, token tk_) ---
        {
            float s = 0.f;
            #pragma unroll
            for (int w2 = 0; w2 < 8; w2++) s += swarp[w2][hh_][tk_];
            s *= 0.125f;
            float mx = s;
            #pragma unroll
            for (int off = 1; off < 16; off <<= 1)
                mx = fmaxf(mx, __shfl_xor_sync(0xffffffffu, mx, off));
            float mprev = mrun[hh_];
            float m_new = fmaxf(mprev, mx);
            float e = expf(s - m_new);
            float ssum = e;
            #pragma unroll
            for (int off = 1; off < 16; off <<= 1)
                ssum += __shfl_xor_sync(0xffffffffu, ssum, off);
            ashs[hh_][tk_] = (u16)(bfpack(e, e) & 0xffffu);
            if (tk_ == 0) {
                float f = expf(mprev - m_new);
                fh[hh_] = f;
                mrun[hh_] = m_new;
                srun[hh_] = srun[hh_] * f + ssum;
            }
        }
        __syncthreads();
        // --- rescale accumulators + wbar MMAs ---
        {
            float fg = fh[g], fg8 = fh[g + 8];
            unsigned a0 = *(const unsigned*)&ashs[g][2 * t];
            unsigned a1 = *(const unsigned*)&ashs[g + 8][2 * t];
            unsigned a2 = *(const unsigned*)&ashs[g][2 * t + 8];
            unsigned a3 = *(const unsigned*)&ashs[g + 8][2 * t + 8];
            #pragma unroll
            for (int nb = 0; nb < 16; nb++) {
                c[nb][0] *= fg;  c[nb][1] *= fg;
                c[nb][2] *= fg8; c[nb][3] *= fg8;
                int e_ = w * 128 + nb * 8 + g;
                unsigned b0 = *(const unsigned*)&fsh[e_][2 * t];
                unsigned b1 = *(const unsigned*)&fsh[e_][2 * t + 8];
                MMA_BF16(c[nb], a0, a1, a2, a3, b0, b1);
            }
        }
    }
    // epilogue: partial wbar + stats
    float* P = dst;
    #pragma unroll
    for (int nb = 0; nb < 16; nb++) {
        int e = w * 128 + nb * 8 + 2 * t;
        P[(size_t)g * Dm + e]           = c[nb][0];
        P[(size_t)g * Dm + e + 1]       = c[nb][1];
        P[(size_t)(g + 8) * Dm + e]     = c[nb][2];
        P[(size_t)(g + 8) * Dm + e + 1] = c[nb][3];
    }
    __syncthreads();
    if (tid < 16) {
        stm[((size_t)sp * Bsz + b) * Hh + tid] = mrun[tid];
        sts[((size_t)sp * Bsz + b) * Hh + tid] = srun[tid];
    }
}

// ---------------- v-projection (merged g/s, flash combine + split reduce) ----
__global__ void k_vproj(const float* __restrict__ wpart,
                        const float* __restrict__ stm, const float* __restrict__ sts,
                        const float* __restrict__ wvg, const float* __restrict__ bvg,
                        const float* __restrict__ wvs, const float* __restrict__ bvs,
                        float* __restrict__ og, float* __restrict__ os)
{
    __shared__ float wsh[1024];
    int b = blockIdx.x, y = blockIdx.y, tid = threadIdx.x;
    int h, NS, spb; const float* base; const float* wv; const float* bv; float* o;
    if (y < 16) { h = y;      NS = 16; spb = 0;  base = wpart;           wv = wvg; bv = bvg; o = og; }
    else        { h = y - 16; NS = 4;  spb = 16; base = wpart + WKV_OFF; wv = wvs; bv = bvs; o = os; }
    // flash combine factors
    float M = -3e38f;
    for (int sp2 = 0; sp2 < NS; sp2++)
        M = fmaxf(M, stm[((size_t)(spb + sp2) * Bsz + b) * Hh + h]);
    float denom = 0.f;
    float fac[16];
    for (int sp2 = 0; sp2 < NS; sp2++) {
        float f = expf(stm[((size_t)(spb + sp2) * Bsz + b) * Hh + h] - M);
        fac[sp2] = f;
        denom += sts[((size_t)(spb + sp2) * Bsz + b) * Hh + h] * f;
    }
    float inv = 1.f / denom;
    float4 acc4 = make_float4(0.f, 0.f, 0.f, 0.f);
    for (int sp2 = 0; sp2 < NS; sp2++) {
        float f = fac[sp2] * inv;
        float4 v = ((const float4*)(base + (((size_t)sp2 * Bsz + b) * Hh + h) * Dm))[tid];
        acc4.x += v.x * f; acc4.y += v.y * f; acc4.z += v.z * f; acc4.w += v.w * f;
    }
    ((float4*)wsh)[tid] = acc4;
    __syncthreads();
    int w = tid >> 5, lane = tid & 31;
    for (int dd = w; dd < 64; dd += 8) {
        int j = h * 64 + dd;
        const float4* wvp = (const float4*)(wv + (size_t)j * Dm);
        float acc = 0.f;
        #pragma unroll
        for (int i = 0; i < 8; i++) {
            float4 a = wvp[i * 32 + lane];
            float4 cc = *(const float4*)&wsh[i * 128 + (lane << 2)];
            acc += a.x * cc.x + a.y * cc.y + a.z * cc.z + a.w * cc.w;
        }
        #pragma unroll
        for (int off = 16; off; off >>= 1) acc += __shfl_xor_sync(0xffffffffu, acc, off);
        if (lane == 0) o[(size_t)b * Dm + j] = acc + bv[j];
    }
}

// ---------------- host helper: split-K GEMM via partials ---------------------
static void gemm(const float* A, int lda, int M, const float* W, int N, int K,
                 int splitK, const float* bias, const float* Res, int ldr,
                 float* C, int ldc, int act, float* part)
{
    dim3 g(N / 64, splitK);
    k_gemm_part<<<g, 256>>>(A, lda, M, W, part, N, K, K / splitK);
    dim3 gr((N + 255) / 256, M);
    k_gemm_reduce<<<gr, 256>>>(part, C, ldc, bias, Res, ldr, M, N, splitK, act);
}

extern "C" void kernel_launch(void* const* d_in, const int* in_sizes, int n_in,
                              void* d_out, int out_size)
{
    const float* frame = (const float*)d_in[0];
    const float* kvs   = (const float*)d_in[1];
    const float* maxi  = (const float*)d_in[2];
    const float* qbase = (const float*)d_in[3];
    const float* role  = (const float*)d_in[4];
    const float* timew = (const float*)d_in[5];
    const float* ln1g  = (const float*)d_in[6];
    const float* ln1b  = (const float*)d_in[7];
    const float* sa_in_w = (const float*)d_in[8];
    const float* sa_in_b = (const float*)d_in[9];
    const float* sa_out_w = (const float*)d_in[10];
    const float* sa_out_b = (const float*)d_in[11];
    const float* ln2g  = (const float*)d_in[12];
    const float* ln2b  = (const float*)d_in[13];
    const float* cg_in_w = (const float*)d_in[14];
    const float* cg_in_b = (const float*)d_in[15];
    const float* cg_out_w = (const float*)d_in[16];
    const float* cg_out_b = (const float*)d_in[17];
    const float* cs_in_w = (const float*)d_in[18];
    const float* cs_in_b = (const float*)d_in[19];
    const float* cs_out_w = (const float*)d_in[20];
    const float* cs_out_b = (const float*)d_in[21];
    const float* ln3g  = (const float*)d_in[22];
    const float* ln3b  = (const float*)d_in[23];
    const float* fw1   = (const float*)d_in[24];
    const float* fb1   = (const float*)d_in[25];
    const float* fw2   = (const float*)d_in[26];
    const float* fb2   = (const float*)d_in[27];
    const float* outg  = (const float*)d_in[28];
    const float* outb  = (const float*)d_in[29];
    const int*   fidx  = (const int*)d_in[30];
    float* outp = (float*)d_out;

    void* sp_;
    cudaGetSymbolAddress(&sp_, g_scratch);
    float* S = (float*)sp_;
    void* fb_; cudaGetSymbolAddress(&fb_, g_frame_bf);
    u16* framebf = (u16*)fb_;
    void* kb_; cudaGetSymbolAddress(&kb_, g_kv_bf);
    u16* kvbf = (u16*)kb_;

    float* mpart = S;                   // 524288
    float* q     = mpart + 524288;      // 65536
    float* x     = q + 65536;           // 65536
    float* t3    = x + 65536;           // 196608
    float* attn  = t3 + 196608;         // 65536
    float* qpg   = attn + 65536;        // 32768
    float* qps   = qpg + 32768;         // 32768
    float* ug    = qps + 32768;         // 524288
    float* us    = ug + 524288;         // 524288
    float* wpart = us + 524288;         // 10485760 (frame 16 + kv 4 chunks)
    float* og    = wpart + 10485760;    // 32768
    float* os    = og + 32768;          // 32768
    float* gpart = os + 32768;          // 3276800
    float* hh    = gpart + 3276800;     // 262144
    float* stm   = hh + 262144;         // 10240
    float* sts   = stm + 10240;         // 10240

    cudaFuncSetAttribute(k_attn, cudaFuncAttributeMaxDynamicSharedMemorySize, 81920);
    const int ATTN_SHM = 33024 + 36864 + 8704 + 768 + 192;

    // init: mean + bf16 conversion + q assembly
    k_mean_part<<<dim3(32, 16), 256>>>(frame, mpart, framebf);
    k_cvt<<<32768, 256>>>(kvs, kvbf);
    k_qinit<<<32, 256>>>(mpart, maxi, qbase, role, timew, fidx, q);

    for (int l = 0; l < 2; l++) {
        const float* l1g = ln1g + l * Dm;   const float* l1b = ln1b + l * Dm;
        const float* siw = sa_in_w + (size_t)l * 3072 * Dm;
        const float* sib = sa_in_b + l * 3072;
        const float* sow = sa_out_w + (size_t)l * Dm * Dm;
        const float* sob = sa_out_b + l * Dm;
        const float* l2g = ln2g + l * Dm;   const float* l2b = ln2b + l * Dm;
        const float* giw = cg_in_w + (size_t)l * 3072 * Dm;
        const float* gib = cg_in_b + l * 3072;
        const float* gow = cg_out_w + (size_t)l * Dm * Dm;
        const float* gob = cg_out_b + l * Dm;
        const float* ciw = cs_in_w + (size_t)l * 3072 * Dm;
        const float* cib = cs_in_b + l * 3072;
        const float* cow = cs_out_w + (size_t)l * Dm * Dm;
        const float* cob = cs_out_b + l * Dm;
        const float* l3g = ln3g + l * Dm;   const float* l3b = ln3b + l * Dm;
        const float* w1 = fw1 + (size_t)l * 4096 * Dm;
        const float* b1 = fb1 + l * 4096;
        const float* w2 = fw2 + (size_t)l * Dm * 4096;
        const float* b2 = fb2 + l * Dm;

        // ---- self-attention (2 tokens) ----
        k_ln<<<64, 256>>>(q, l1g, l1b, x);
        gemm(x, 1024, 64, siw, 3072, 1024, 16, sib, nullptr, 0, t3, 3072, 0, gpart);
        k_selfattn<<<dim3(32, 16), 64>>>(t3, attn);
        gemm(attn, 1024, 64, sow, 1024, 1024, 16, sob, q, 1024, q, 1024, 0, gpart);

        // ---- cross-attention (folded K/V, flash-fused) ----
        k_ln<<<64, 256>>>(q, l2g, l2b, x);
        gemm(x,        2048, 32, giw, 1024, 1024, 16, gib, nullptr, 0, qpg, 1024, 0, gpart);
        gemm(x + 1024, 2048, 32, ciw, 1024, 1024, 16, cib, nullptr, 0, qps, 1024, 0, gpart);
        k_ufold<<<dim3(16, 8), 128>>>(qpg, giw + 1024 * 1024, ug);
        k_ufold<<<dim3(16, 8), 128>>>(qps, ciw + 1024 * 1024, us);
        k_attn<<<dim3(32, 20), 256, ATTN_SHM>>>(framebf, kvbf, ug, us, wpart, stm, sts);
        k_vproj<<<dim3(32, 32), 256>>>(wpart, stm, sts,
                                       giw + 2 * 1024 * 1024, gib + 2048,
                                       ciw + 2 * 1024 * 1024, cib + 2048, og, os);
        gemm(og, 1024, 32, gow, 1024, 1024, 16, gob, q,        2048, q,        2048, 0, gpart);
        gemm(os, 1024, 32, cow, 1024, 1024, 16, cob, q + 1024, 2048, q + 1024, 2048, 0, gpart);

        // ---- FFN ----
        k_ln<<<64, 256>>>(q, l3g, l3b, x);
        gemm(x, 1024, 64, w1, 4096, 1024, 8, b1, nullptr, 0, hh, 4096, 1, gpart);
        gemm(hh, 4096, 64, w2, 1024, 4096, 32, b2, q, 1024, q, 1024, 0, gpart);
    }

    // final LN -> d_out (B,2,D) contiguous
    k_ln<<<64, 256>>>(q, outg, outb, outp);
}